// round 1
// baseline (speedup 1.0000x reference)
#include <cuda_runtime.h>
#include <math.h>

// Problem constants
#define B_ 32
#define S_ 128
#define H_ 512
#define K_ 8

#define TILE 128
#define BK 8

// Scratch (device globals — no runtime allocation allowed)
__device__ float g_proj[2ull * 4096 * 4096];      // [branch][B*S][K*H]  134 MB
__device__ float g_c2[2ull * 32 * 1024 * 128];    // [br*32+b][s*8+k][t]  33.5 MB
__device__ float g_score[2ull * 32 * 128 * 128];  // [br*32+b][s][t]      4 MB

// ---------------------------------------------------------------------------
// Generic single-buffered SGEMM tile body: 128x128 block tile, BK=8, 256 thr,
// 8x8 per-thread microtile. A is [M,Kd] row-major. B is either
//   BT=false: [Kd,N] row-major (NN)
//   BT=true : [N,Kd] row-major (NT, i.e. C = A * B^T)
// All dims assumed multiples of tile sizes (true for this problem).
// ---------------------------------------------------------------------------
template <bool BT>
__device__ __forceinline__ void sgemm_body(const float* __restrict__ A, int lda,
                                           const float* __restrict__ B, int ldb,
                                           float (&acc)[8][8], int Kd,
                                           int block_m, int block_n) {
    __shared__ float As[BK][TILE];
    __shared__ float Bs[BK][TILE];

    const int tid = threadIdx.x;
    const int tx = tid & 15;   // 0..15 -> n
    const int ty = tid >> 4;   // 0..15 -> m

    // A tile loader: 128 rows x 8 k-cols, one float4 along k per thread
    const int aRow = tid >> 1;
    const int aCol = (tid & 1) * 4;
    const float* Aptr = A + (size_t)(block_m + aRow) * lda + aCol;

    const float* Bptr;
    int bRow, bCol;
    if (BT) {
        bRow = tid >> 1;           // n index
        bCol = (tid & 1) * 4;      // k index
        Bptr = B + (size_t)(block_n + bRow) * ldb + bCol;
    } else {
        bRow = tid >> 5;           // k index (0..7)
        bCol = (tid & 31) * 4;     // n index
        Bptr = B + (size_t)bRow * ldb + block_n + bCol;
    }

    for (int k0 = 0; k0 < Kd; k0 += BK) {
        float4 av = *(const float4*)(Aptr + k0);
        As[aCol + 0][aRow] = av.x;
        As[aCol + 1][aRow] = av.y;
        As[aCol + 2][aRow] = av.z;
        As[aCol + 3][aRow] = av.w;
        if (BT) {
            float4 bv = *(const float4*)(Bptr + k0);
            Bs[bCol + 0][bRow] = bv.x;
            Bs[bCol + 1][bRow] = bv.y;
            Bs[bCol + 2][bRow] = bv.z;
            Bs[bCol + 3][bRow] = bv.w;
        } else {
            float4 bv = *(const float4*)(Bptr + (size_t)k0 * ldb);
            *(float4*)&Bs[bRow][bCol] = bv;
        }
        __syncthreads();

#pragma unroll
        for (int kk = 0; kk < BK; kk++) {
            float4 a0 = *(const float4*)&As[kk][ty * 8];
            float4 a1 = *(const float4*)&As[kk][ty * 8 + 4];
            float4 b0 = *(const float4*)&Bs[kk][tx * 8];
            float4 b1 = *(const float4*)&Bs[kk][tx * 8 + 4];
            float a[8] = {a0.x, a0.y, a0.z, a0.w, a1.x, a1.y, a1.z, a1.w};
            float b[8] = {b0.x, b0.y, b0.z, b0.w, b1.x, b1.y, b1.z, b1.w};
#pragma unroll
            for (int i = 0; i < 8; i++)
#pragma unroll
                for (int j = 0; j < 8; j++) acc[i][j] = fmaf(a[i], b[j], acc[i][j]);
        }
        __syncthreads();
    }
}

// ---------------------------------------------------------------------------
// GEMM1: proj[br] = aspect[4096,512] @ G_br[512,4096]   (NN)
// grid (32, 32, 2), block 256
// ---------------------------------------------------------------------------
__global__ __launch_bounds__(256) void k_gemm1(const float* __restrict__ aspect,
                                               const float* __restrict__ Gap,
                                               const float* __restrict__ Gpa) {
    const int br = blockIdx.z;
    const float* Bm = br ? Gpa : Gap;
    const int block_m = blockIdx.y * TILE;
    const int block_n = blockIdx.x * TILE;
    float acc[8][8] = {};
    sgemm_body<false>(aspect, H_, Bm, K_ * H_, acc, H_, block_m, block_n);

    float* C = g_proj + (size_t)br * 4096 * 4096;
    const int tx = threadIdx.x & 15, ty = threadIdx.x >> 4;
#pragma unroll
    for (int i = 0; i < 8; i++) {
        float* row = C + (size_t)(block_m + ty * 8 + i) * 4096 + block_n + tx * 8;
        *(float4*)row = make_float4(acc[i][0], acc[i][1], acc[i][2], acc[i][3]);
        *(float4*)(row + 4) = make_float4(acc[i][4], acc[i][5], acc[i][6], acc[i][7]);
    }
}

// ---------------------------------------------------------------------------
// GEMM2: per (br,b): C2 = proj_b[1024,512] @ right_b^T[512,128]  (NT)
// grid (1, 8, 64), block 256 ; z = br*32 + b
// ---------------------------------------------------------------------------
__global__ __launch_bounds__(256) void k_gemm2(const float* __restrict__ aspect,
                                               const float* __restrict__ polarity) {
    const int z = blockIdx.z;
    const int br = z >> 5, b = z & 31;
    const float* right = br ? aspect : polarity;
    const float* A = g_proj + (size_t)br * 4096 * 4096 + (size_t)b * 128 * 4096;
    const float* Bm = right + (size_t)b * S_ * H_;
    const int block_m = blockIdx.y * TILE;
    float acc[8][8] = {};
    sgemm_body<true>(A, H_, Bm, H_, acc, H_, block_m, 0);

    float* C = g_c2 + (size_t)z * 1024 * 128;
    const int tx = threadIdx.x & 15, ty = threadIdx.x >> 4;
#pragma unroll
    for (int i = 0; i < 8; i++) {
        float* row = C + (size_t)(block_m + ty * 8 + i) * 128 + tx * 8;
        *(float4*)row = make_float4(acc[i][0], acc[i][1], acc[i][2], acc[i][3]);
        *(float4*)(row + 4) = make_float4(acc[i][4], acc[i][5], acc[i][6], acc[i][7]);
    }
}

// ---------------------------------------------------------------------------
// score[z,s,t] = sum_k v_br[k] * tanh(C2[z, s*8+k, t])
// ---------------------------------------------------------------------------
__global__ __launch_bounds__(256) void k_score(const float* __restrict__ va,
                                               const float* __restrict__ vp) {
    const int idx = blockIdx.x * blockDim.x + threadIdx.x;
    if (idx >= 2 * 32 * 128 * 128) return;
    const int t = idx & 127;
    const int s = (idx >> 7) & 127;
    const int z = idx >> 14;
    const int br = z >> 5;
    const float* v = br ? vp : va;
    const float* c2 = g_c2 + (size_t)z * 1024 * 128 + (size_t)s * 8 * 128 + t;
    float sc = 0.f;
#pragma unroll
    for (int k = 0; k < K_; k++) sc += v[k] * tanhf(c2[(size_t)k * 128]);
    g_score[idx] = sc;
}

// ---------------------------------------------------------------------------
// In-place softmax over rows of length 128. One warp per row.
// ---------------------------------------------------------------------------
__global__ __launch_bounds__(256) void k_softmax() {
    const int warp = (blockIdx.x * blockDim.x + threadIdx.x) >> 5;
    const int lane = threadIdx.x & 31;
    if (warp >= 2 * 32 * 128) return;
    float* row = g_score + (size_t)warp * 128;
    float vals[4];
    float m = -1e30f;
#pragma unroll
    for (int i = 0; i < 4; i++) {
        vals[i] = row[lane + i * 32];
        m = fmaxf(m, vals[i]);
    }
#pragma unroll
    for (int o = 16; o; o >>= 1) m = fmaxf(m, __shfl_xor_sync(0xffffffffu, m, o));
    float ssum = 0.f;
#pragma unroll
    for (int i = 0; i < 4; i++) {
        vals[i] = expf(vals[i] - m);
        ssum += vals[i];
    }
#pragma unroll
    for (int o = 16; o; o >>= 1) ssum += __shfl_xor_sync(0xffffffffu, ssum, o);
    const float inv = 1.f / ssum;
#pragma unroll
    for (int i = 0; i < 4; i++) row[lane + i * 32] = vals[i] * inv;
}

// ---------------------------------------------------------------------------
// GEMM3: out = bias + attn[128,128] @ values[128,512]  (NN, bias epilogue)
// grid (4, 1, 64), block 256 ; z = br*32 + b
// ---------------------------------------------------------------------------
__global__ __launch_bounds__(256) void k_gemm3(const float* __restrict__ aspect,
                                               const float* __restrict__ polarity,
                                               float* __restrict__ out) {
    const int z = blockIdx.z;
    const int br = z >> 5, b = z & 31;
    const float* A = g_score + (size_t)z * 128 * 128;
    const float* Bv = (br ? aspect : polarity) + (size_t)b * S_ * H_;
    const float* bias = (br ? polarity : aspect) + (size_t)b * S_ * H_;
    float* C = out + (size_t)br * B_ * S_ * H_ + (size_t)b * S_ * H_;
    const int block_n = blockIdx.x * TILE;
    float acc[8][8] = {};
    sgemm_body<false>(A, 128, Bv, H_, acc, 128, 0, block_n);

    const int tx = threadIdx.x & 15, ty = threadIdx.x >> 4;
#pragma unroll
    for (int i = 0; i < 8; i++) {
        const size_t off = (size_t)(ty * 8 + i) * H_ + block_n + tx * 8;
        float4 b0 = *(const float4*)(bias + off);
        float4 b1 = *(const float4*)(bias + off + 4);
        *(float4*)(C + off) = make_float4(b0.x + acc[i][0], b0.y + acc[i][1],
                                          b0.z + acc[i][2], b0.w + acc[i][3]);
        *(float4*)(C + off + 4) = make_float4(b0.w * 0.f + b1.x + acc[i][4],
                                              b1.y + acc[i][5], b1.z + acc[i][6],
                                              b1.w + acc[i][7]);
    }
}

// ---------------------------------------------------------------------------
extern "C" void kernel_launch(void* const* d_in, const int* in_sizes, int n_in,
                              void* d_out, int out_size) {
    const float* aspect = (const float*)d_in[0];
    const float* polarity = (const float*)d_in[1];
    const float* Gap = (const float*)d_in[2];
    const float* Gpa = (const float*)d_in[3];
    const float* va = (const float*)d_in[4];
    const float* vp = (const float*)d_in[5];
    float* out = (float*)d_out;

    k_gemm1<<<dim3(32, 32, 2), 256>>>(aspect, Gap, Gpa);
    k_gemm2<<<dim3(1, 8, 64), 256>>>(aspect, polarity);
    k_score<<<4096, 256>>>(va, vp);
    k_softmax<<<1024, 256>>>();
    k_gemm3<<<dim3(4, 1, 64), 256>>>(aspect, polarity, out);
}

// round 2
// speedup vs baseline: 1.1498x; 1.1498x over previous
#include <cuda_runtime.h>
#include <math.h>

// Problem constants
#define B_ 32
#define S_ 128
#define H_ 512
#define K_ 8

#define TILE 128
#define BK 8

// Scratch (device globals — no runtime allocation allowed)
__device__ float g_proj[2ull * 4096 * 4096];      // [branch][B*S][K*H]  134 MB
__device__ float g_attn[2ull * 32 * 128 * 128];   // softmaxed attention  4 MB

// ---------------------------------------------------------------------------
// Packed f32x2 helpers (Blackwell FFMA2 — 2 FMAs per instruction)
// ---------------------------------------------------------------------------
__device__ __forceinline__ void ffma2(unsigned long long& d, unsigned long long a,
                                      unsigned long long b) {
    asm("fma.rn.f32x2 %0, %1, %2, %0;" : "+l"(d) : "l"(a), "l"(b));
}
__device__ __forceinline__ unsigned long long dup2(float a) {
    unsigned long long r;
    asm("mov.b64 %0, {%1, %1};" : "=l"(r) : "f"(a));
    return r;
}
__device__ __forceinline__ float2 unpack2(unsigned long long v) {
    float2 f;
    asm("mov.b64 {%0, %1}, %2;" : "=f"(f.x), "=f"(f.y) : "l"(v));
    return f;
}

// ---------------------------------------------------------------------------
// Double-buffered SGEMM tile body with FFMA2 accumulators.
// 128x128 block tile, BK=8, 256 threads, 8x8 per-thread microtile.
// A: [M,Kd] row-major.  B: BT=false -> [Kd,N] row-major (NN)
//                        BT=true  -> [N,Kd] row-major (NT, C = A * B^T)
// acc[i][j] packs C columns (2j, 2j+1) for microtile row i.
// ---------------------------------------------------------------------------
template <bool BT>
__device__ __forceinline__ void sgemm_db(const float* __restrict__ A, int lda,
                                         const float* __restrict__ B, int ldb,
                                         unsigned long long (&acc)[8][4], int Kd,
                                         int block_m, int block_n) {
    __shared__ float As[2][BK][TILE];
    __shared__ float Bs[2][BK][TILE];

    const int tid = threadIdx.x;
    const int tx = tid & 15;
    const int ty = tid >> 4;

    const int aRow = tid >> 1;
    const int aCol = (tid & 1) * 4;
    const float* Aptr = A + (size_t)(block_m + aRow) * lda + aCol;

    const float* Bptr;
    int bRow, bCol;
    if (BT) {
        bRow = tid >> 1;
        bCol = (tid & 1) * 4;
        Bptr = B + (size_t)(block_n + bRow) * ldb + bCol;
    } else {
        bRow = tid >> 5;
        bCol = (tid & 31) * 4;
        Bptr = B + (size_t)bRow * ldb + block_n + bCol;
    }

    // Preload tile 0
    float4 av = *(const float4*)Aptr;
    float4 bv = *(const float4*)Bptr;
    As[0][aCol + 0][aRow] = av.x;
    As[0][aCol + 1][aRow] = av.y;
    As[0][aCol + 2][aRow] = av.z;
    As[0][aCol + 3][aRow] = av.w;
    if (BT) {
        Bs[0][bCol + 0][bRow] = bv.x;
        Bs[0][bCol + 1][bRow] = bv.y;
        Bs[0][bCol + 2][bRow] = bv.z;
        Bs[0][bCol + 3][bRow] = bv.w;
    } else {
        *(float4*)&Bs[0][bRow][bCol] = bv;
    }
    __syncthreads();

    int buf = 0;
#pragma unroll 1
    for (int k0 = 0; k0 < Kd; k0 += BK) {
        const bool hn = (k0 + BK) < Kd;
        if (hn) {
            av = *(const float4*)(Aptr + k0 + BK);
            bv = BT ? *(const float4*)(Bptr + k0 + BK)
                    : *(const float4*)(Bptr + (size_t)(k0 + BK) * ldb);
        }

#pragma unroll
        for (int kk = 0; kk < BK; kk++) {
            const float4 a0 = *(const float4*)&As[buf][kk][ty * 8];
            const float4 a1 = *(const float4*)&As[buf][kk][ty * 8 + 4];
            const ulonglong2 bq0 = *(const ulonglong2*)&Bs[buf][kk][tx * 8];
            const ulonglong2 bq1 = *(const ulonglong2*)&Bs[buf][kk][tx * 8 + 4];
            unsigned long long b2[4] = {bq0.x, bq0.y, bq1.x, bq1.y};
            unsigned long long a2[8] = {dup2(a0.x), dup2(a0.y), dup2(a0.z), dup2(a0.w),
                                        dup2(a1.x), dup2(a1.y), dup2(a1.z), dup2(a1.w)};
#pragma unroll
            for (int i = 0; i < 8; i++)
#pragma unroll
                for (int j = 0; j < 4; j++) ffma2(acc[i][j], a2[i], b2[j]);
        }

        if (hn) {
            const int nb = buf ^ 1;
            As[nb][aCol + 0][aRow] = av.x;
            As[nb][aCol + 1][aRow] = av.y;
            As[nb][aCol + 2][aRow] = av.z;
            As[nb][aCol + 3][aRow] = av.w;
            if (BT) {
                Bs[nb][bCol + 0][bRow] = bv.x;
                Bs[nb][bCol + 1][bRow] = bv.y;
                Bs[nb][bCol + 2][bRow] = bv.z;
                Bs[nb][bCol + 3][bRow] = bv.w;
            } else {
                *(float4*)&Bs[nb][bRow][bCol] = bv;
            }
            __syncthreads();
        }
        buf ^= 1;
    }
}

// ---------------------------------------------------------------------------
// GEMM1: proj[br] = aspect[4096,512] @ G_br[512,4096]   (NN)
// grid (32, 32, 2), block 256
// ---------------------------------------------------------------------------
__global__ __launch_bounds__(256) void k_gemm1(const float* __restrict__ aspect,
                                               const float* __restrict__ Gap,
                                               const float* __restrict__ Gpa) {
    const int br = blockIdx.z;
    const float* Bm = br ? Gpa : Gap;
    const int block_m = blockIdx.y * TILE;
    const int block_n = blockIdx.x * TILE;
    unsigned long long acc[8][4] = {};
    sgemm_db<false>(aspect, H_, Bm, K_ * H_, acc, H_, block_m, block_n);

    float* C = g_proj + (size_t)br * 4096 * 4096;
    const int tx = threadIdx.x & 15, ty = threadIdx.x >> 4;
#pragma unroll
    for (int i = 0; i < 8; i++) {
        float* row = C + (size_t)(block_m + ty * 8 + i) * 4096 + block_n + tx * 8;
        float2 p0 = unpack2(acc[i][0]);
        float2 p1 = unpack2(acc[i][1]);
        float2 p2 = unpack2(acc[i][2]);
        float2 p3 = unpack2(acc[i][3]);
        *(float4*)row = make_float4(p0.x, p0.y, p1.x, p1.y);
        *(float4*)(row + 4) = make_float4(p2.x, p2.y, p3.x, p3.y);
    }
}

// ---------------------------------------------------------------------------
// GEMM2 fused: C2 = proj_b[1024,512] @ right_b^T  (NT), then in-epilogue
// score[s,t] = sum_k v[k]*tanh(C2[s*8+k, t]) and row softmax -> g_attn.
// Each thread's 8 accumulator rows are exactly the 8 k-values of one s.
// grid (1, 8, 64), block 256 ; z = br*32 + b
// ---------------------------------------------------------------------------
__global__ __launch_bounds__(256) void k_gemm2(const float* __restrict__ aspect,
                                               const float* __restrict__ polarity,
                                               const float* __restrict__ va,
                                               const float* __restrict__ vp) {
    const int z = blockIdx.z;
    const int br = z >> 5, b = z & 31;
    const float* right = br ? aspect : polarity;
    const float* A = g_proj + (size_t)br * 4096 * 4096 + (size_t)b * 128 * 4096;
    const float* Bm = right + (size_t)b * S_ * H_;
    const int block_m = blockIdx.y * TILE;
    unsigned long long acc[8][4] = {};
    sgemm_db<true>(A, 512, Bm, H_, acc, H_, block_m, 0);

    const float* v = br ? vp : va;
    float vv[8];
#pragma unroll
    for (int i = 0; i < 8; i++) vv[i] = v[i];

    const int tx = threadIdx.x & 15, ty = threadIdx.x >> 4;
    float sc[8] = {0.f, 0.f, 0.f, 0.f, 0.f, 0.f, 0.f, 0.f};
#pragma unroll
    for (int i = 0; i < 8; i++) {
#pragma unroll
        for (int jq = 0; jq < 4; jq++) {
            float2 p = unpack2(acc[i][jq]);
            sc[2 * jq] += vv[i] * tanhf(p.x);
            sc[2 * jq + 1] += vv[i] * tanhf(p.y);
        }
    }

    // Row softmax: row s owned by 16 consecutive lanes (same ty half-warp).
    float m = -1e30f;
#pragma unroll
    for (int j = 0; j < 8; j++) m = fmaxf(m, sc[j]);
#pragma unroll
    for (int o = 8; o; o >>= 1) m = fmaxf(m, __shfl_xor_sync(0xffffffffu, m, o));
    float ssum = 0.f;
#pragma unroll
    for (int j = 0; j < 8; j++) {
        sc[j] = expf(sc[j] - m);
        ssum += sc[j];
    }
#pragma unroll
    for (int o = 8; o; o >>= 1) ssum += __shfl_xor_sync(0xffffffffu, ssum, o);
    const float inv = 1.f / ssum;

    const int srow = (block_m >> 3) + ty;
    float* out = g_attn + (size_t)z * (128 * 128) + (size_t)srow * 128 + tx * 8;
    *(float4*)out = make_float4(sc[0] * inv, sc[1] * inv, sc[2] * inv, sc[3] * inv);
    *(float4*)(out + 4) = make_float4(sc[4] * inv, sc[5] * inv, sc[6] * inv, sc[7] * inv);
}

// ---------------------------------------------------------------------------
// GEMM3: out = bias + attn[128,128] @ values[128,512]  (NN, bias epilogue)
// grid (4, 1, 64), block 256 ; z = br*32 + b
// ---------------------------------------------------------------------------
__global__ __launch_bounds__(256) void k_gemm3(const float* __restrict__ aspect,
                                               const float* __restrict__ polarity,
                                               float* __restrict__ out) {
    const int z = blockIdx.z;
    const int br = z >> 5, b = z & 31;
    const float* A = g_attn + (size_t)z * (128 * 128);
    const float* Bv = (br ? aspect : polarity) + (size_t)b * S_ * H_;
    const float* bias = (br ? polarity : aspect) + (size_t)b * S_ * H_;
    float* C = out + (size_t)br * B_ * S_ * H_ + (size_t)b * S_ * H_;
    const int block_n = blockIdx.x * TILE;
    unsigned long long acc[8][4] = {};
    sgemm_db<false>(A, 128, Bv, H_, acc, 128, 0, block_n);

    const int tx = threadIdx.x & 15, ty = threadIdx.x >> 4;
#pragma unroll
    for (int i = 0; i < 8; i++) {
        const size_t off = (size_t)(ty * 8 + i) * H_ + block_n + tx * 8;
        float4 b0 = *(const float4*)(bias + off);
        float4 b1 = *(const float4*)(bias + off + 4);
        float2 p0 = unpack2(acc[i][0]);
        float2 p1 = unpack2(acc[i][1]);
        float2 p2 = unpack2(acc[i][2]);
        float2 p3 = unpack2(acc[i][3]);
        *(float4*)(C + off) =
            make_float4(b0.x + p0.x, b0.y + p0.y, b0.z + p1.x, b0.w + p1.y);
        *(float4*)(C + off + 4) =
            make_float4(b1.x + p2.x, b1.y + p2.y, b1.z + p3.x, b1.w + p3.y);
    }
}

// ---------------------------------------------------------------------------
extern "C" void kernel_launch(void* const* d_in, const int* in_sizes, int n_in,
                              void* d_out, int out_size) {
    const float* aspect = (const float*)d_in[0];
    const float* polarity = (const float*)d_in[1];
    const float* Gap = (const float*)d_in[2];
    const float* Gpa = (const float*)d_in[3];
    const float* va = (const float*)d_in[4];
    const float* vp = (const float*)d_in[5];
    float* out = (float*)d_out;

    k_gemm1<<<dim3(32, 32, 2), 256>>>(aspect, Gap, Gpa);
    k_gemm2<<<dim3(1, 8, 64), 256>>>(aspect, polarity, va, vp);
    k_gemm3<<<dim3(4, 1, 64), 256>>>(aspect, polarity, out);
}

// round 4
// speedup vs baseline: 1.2504x; 1.0874x over previous
#include <cuda_runtime.h>
#include <math.h>
#include <stdint.h>

// Problem constants
#define B_ 32
#define S_ 128
#define H_ 512
#define K_ 8

#define TILE 128
#define BK 8

// Scratch (device globals — no runtime allocation allowed)
__device__ float g_proj[2ull * 4096 * 4096];     // [branch][B*S][K*H]  134 MB
__device__ float g_attn[2ull * 32 * 128 * 128];  // softmaxed attention  4 MB
__device__ float g_ahi[4096ull * 512];           // aspect tf32-hi
__device__ float g_alo[4096ull * 512];           // aspect tf32-lo
__device__ float g_bhi[2ull * 4096 * 512];       // G^T tf32-hi per branch
__device__ float g_blo[2ull * 4096 * 512];       // G^T tf32-lo per branch

// ===========================================================================
// Helpers
// ===========================================================================
__device__ __forceinline__ uint32_t smem_to_u32(const void* p) {
    uint32_t a;
    asm("{ .reg .u64 t; cvta.to.shared.u64 t, %1; cvt.u32.u64 %0, t; }"
        : "=r"(a) : "l"(p));
    return a;
}

__device__ __forceinline__ void cp16(uint32_t s, const float* g) {
    asm volatile(
        "{ .reg .u64 gg; cvta.to.global.u64 gg, %1;"
        "  cp.async.cg.shared.global [%0], [gg], 16; }"
        :: "r"(s), "l"(g));
}
__device__ __forceinline__ void cp_commit() {
    asm volatile("cp.async.commit_group;" ::: "memory");
}
__device__ __forceinline__ void cp_wait0() {
    asm volatile("cp.async.wait_group 0;" ::: "memory");
}

// mma.sync tf32 m16n8k8 (sm_80 baseline — maps to HMMA on sm_103)
__device__ __forceinline__ void mma_tf32(float (&d)[4], const uint32_t (&a)[4],
                                         const uint32_t (&b)[2]) {
    asm volatile(
        "mma.sync.aligned.m16n8k8.row.col.f32.tf32.tf32.f32 "
        "{%0,%1,%2,%3}, {%4,%5,%6,%7}, {%8,%9}, {%0,%1,%2,%3};"
        : "+f"(d[0]), "+f"(d[1]), "+f"(d[2]), "+f"(d[3])
        : "r"(a[0]), "r"(a[1]), "r"(a[2]), "r"(a[3]), "r"(b[0]), "r"(b[1]));
}

// tf32 split: x = hi + lo (both exact tf32)
__device__ __forceinline__ void split_tf32(float x, float& hi, float& lo) {
    uint32_t hb;
    asm("cvt.rna.tf32.f32 %0, %1;" : "=r"(hb) : "f"(x));
    float hf = __uint_as_float(hb);
    float l = x - hf;
    uint32_t lb;
    asm("cvt.rna.tf32.f32 %0, %1;" : "=r"(lb) : "f"(l));
    hi = hf;
    lo = __uint_as_float(lb);
}

// ===========================================================================
// Prep kernels
// ===========================================================================
__global__ __launch_bounds__(256) void k_prep_a(const float* __restrict__ x) {
    const int i = blockIdx.x * blockDim.x + threadIdx.x;
    if (i >= 4096 * 512 / 4) return;
    float4 v = ((const float4*)x)[i];
    float4 h, l;
    split_tf32(v.x, h.x, l.x);
    split_tf32(v.y, h.y, l.y);
    split_tf32(v.z, h.z, l.z);
    split_tf32(v.w, h.w, l.w);
    ((float4*)g_ahi)[i] = h;
    ((float4*)g_alo)[i] = l;
}

// Transpose G[br][512,4096] -> GT[br][4096,512] with tf32 hi/lo split
__global__ __launch_bounds__(256) void k_prep_g(const float* __restrict__ Gap,
                                                const float* __restrict__ Gpa) {
    __shared__ float t[32][33];
    const int br = blockIdx.z;
    const float* G = br ? Gpa : Gap;
    const int n0 = blockIdx.x * 32, k0 = blockIdx.y * 32;
#pragma unroll
    for (int j = 0; j < 4; j++)
        t[threadIdx.y + j * 8][threadIdx.x] =
            G[(size_t)(k0 + threadIdx.y + j * 8) * 4096 + n0 + threadIdx.x];
    __syncthreads();
    float* GH = g_bhi + (size_t)br * 4096 * 512;
    float* GL = g_blo + (size_t)br * 4096 * 512;
#pragma unroll
    for (int j = 0; j < 4; j++) {
        const int n = n0 + threadIdx.y + j * 8;
        const int k = k0 + threadIdx.x;
        float hi, lo;
        split_tf32(t[threadIdx.x][threadIdx.y + j * 8], hi, lo);
        GH[(size_t)n * 512 + k] = hi;
        GL[(size_t)n * 512 + k] = lo;
    }
}

// ===========================================================================
// GEMM1 (mma.sync tf32, 3x split, NT): proj[br] = A[4096,512] @ GT[br]^T
// CTA tile 128x128, 8 warps (warp tile 32x64), K chunk 16, cp.async 2-stage.
// Smem per matrix per buffer: [128 rows][20 floats] (stride-20 pad).
// ===========================================================================
#define G1_MAT_F 2560          // 128*20 floats per matrix
#define G1_BUF_F (4 * G1_MAT_F)
#define G1_SMEM_BYTES (2 * G1_BUF_F * 4)

__global__ __launch_bounds__(256) void k_gemm1_mma() {
    extern __shared__ float sm[];
    const int tid = threadIdx.x;
    const int wid = tid >> 5, lane = tid & 31;
    const int g = lane >> 2, tig = lane & 3;
    const int wm = (wid & 3) * 32;   // warp m-offset within CTA tile
    const int wn = (wid >> 2) * 64;  // warp n-offset

    const int br = blockIdx.z;
    const int m0 = blockIdx.y * 128;
    const int n0 = blockIdx.x * 128;

    const float* Ah = g_ahi + (size_t)m0 * 512;
    const float* Al = g_alo + (size_t)m0 * 512;
    const float* Bh = g_bhi + (size_t)br * 4096 * 512 + (size_t)n0 * 512;
    const float* Bl = g_blo + (size_t)br * 4096 * 512 + (size_t)n0 * 512;

    const uint32_t sbase = smem_to_u32(sm);

    float acc[2][8][4] = {};

    // --- chunk loader: 4 matrices x 128 rows x 16 k-floats, via cp.async ---
    const int ldr = (tid * 2) >> 2;        // row for this thread's 1st chunk
    const int ldq = ((tid * 2) & 3) * 4;   // k-quad (floats)
#define LOAD_CHUNK(kc, buf)                                                     \
    {                                                                           \
        const int k0_ = (kc) * 16;                                              \
        const uint32_t sb_ = sbase + (buf) * (G1_BUF_F * 4);                    \
        _Pragma("unroll") for (int j = 0; j < 2; j++) {                         \
            const int idx = tid * 2 + j;                                        \
            const int r = idx >> 2;                                             \
            const int q = (idx & 3) * 4;                                        \
            const uint32_t so = (uint32_t)(r * 20 + q) * 4;                     \
            cp16(sb_ + 0 * (G1_MAT_F * 4) + so, Ah + (size_t)r * 512 + k0_ + q);\
            cp16(sb_ + 1 * (G1_MAT_F * 4) + so, Al + (size_t)r * 512 + k0_ + q);\
            cp16(sb_ + 2 * (G1_MAT_F * 4) + so, Bh + (size_t)r * 512 + k0_ + q);\
            cp16(sb_ + 3 * (G1_MAT_F * 4) + so, Bl + (size_t)r * 512 + k0_ + q);\
        }                                                                       \
    }

    (void)ldr; (void)ldq;

    LOAD_CHUNK(0, 0);
    cp_commit();
    cp_wait0();
    __syncthreads();

#pragma unroll 1
    for (int c = 0; c < 32; c++) {
        const int buf = c & 1;
        if (c < 31) {
            LOAD_CHUNK(c + 1, buf ^ 1);
            cp_commit();
        }

        const float* S = sm + buf * G1_BUF_F;
        const float* sAh = S;
        const float* sAl = S + G1_MAT_F;
        const float* sBh = S + 2 * G1_MAT_F;
        const float* sBl = S + 3 * G1_MAT_F;

#pragma unroll
        for (int ks = 0; ks < 2; ks++) {
            const int kb = ks * 8;
            uint32_t ah[2][4], al[2][4], bh[8][2], bl[8][2];
#pragma unroll
            for (int fm = 0; fm < 2; fm++) {
                const int mr = wm + fm * 16 + g;
                ah[fm][0] = __float_as_uint(sAh[mr * 20 + kb + tig]);
                ah[fm][1] = __float_as_uint(sAh[(mr + 8) * 20 + kb + tig]);
                ah[fm][2] = __float_as_uint(sAh[mr * 20 + kb + tig + 4]);
                ah[fm][3] = __float_as_uint(sAh[(mr + 8) * 20 + kb + tig + 4]);
                al[fm][0] = __float_as_uint(sAl[mr * 20 + kb + tig]);
                al[fm][1] = __float_as_uint(sAl[(mr + 8) * 20 + kb + tig]);
                al[fm][2] = __float_as_uint(sAl[mr * 20 + kb + tig + 4]);
                al[fm][3] = __float_as_uint(sAl[(mr + 8) * 20 + kb + tig + 4]);
            }
#pragma unroll
            for (int fn = 0; fn < 8; fn++) {
                const int nr = wn + fn * 8 + g;
                bh[fn][0] = __float_as_uint(sBh[nr * 20 + kb + tig]);
                bh[fn][1] = __float_as_uint(sBh[nr * 20 + kb + tig + 4]);
                bl[fn][0] = __float_as_uint(sBl[nr * 20 + kb + tig]);
                bl[fn][1] = __float_as_uint(sBl[nr * 20 + kb + tig + 4]);
            }
#pragma unroll
            for (int fm = 0; fm < 2; fm++)
#pragma unroll
                for (int fn = 0; fn < 8; fn++) {
                    mma_tf32(acc[fm][fn], ah[fm], bh[fn]);
                    mma_tf32(acc[fm][fn], ah[fm], bl[fn]);
                    mma_tf32(acc[fm][fn], al[fm], bh[fn]);
                }
        }

        if (c < 31) {
            cp_wait0();
            __syncthreads();
        }
    }

    // Epilogue: write fp32 accumulators to g_proj
    float* C = g_proj + (size_t)br * 4096 * 4096;
#pragma unroll
    for (int fm = 0; fm < 2; fm++) {
        const int row = m0 + wm + fm * 16 + g;
#pragma unroll
        for (int fn = 0; fn < 8; fn++) {
            const int col = n0 + wn + fn * 8 + tig * 2;
            *(float2*)&C[(size_t)row * 4096 + col] =
                make_float2(acc[fm][fn][0], acc[fm][fn][1]);
            *(float2*)&C[(size_t)(row + 8) * 4096 + col] =
                make_float2(acc[fm][fn][2], acc[fm][fn][3]);
        }
    }
}

// ===========================================================================
// FFMA2 helpers + double-buffered SGEMM body (GEMM2 / GEMM3)
// ===========================================================================
__device__ __forceinline__ void ffma2(unsigned long long& d, unsigned long long a,
                                      unsigned long long b) {
    asm("fma.rn.f32x2 %0, %1, %2, %0;" : "+l"(d) : "l"(a), "l"(b));
}
__device__ __forceinline__ unsigned long long dup2(float a) {
    unsigned long long r;
    asm("mov.b64 %0, {%1, %1};" : "=l"(r) : "f"(a));
    return r;
}
__device__ __forceinline__ float2 unpack2(unsigned long long v) {
    float2 f;
    asm("mov.b64 {%0, %1}, %2;" : "=f"(f.x), "=f"(f.y) : "l"(v));
    return f;
}

template <bool BT>
__device__ __forceinline__ void sgemm_db(const float* __restrict__ A, int lda,
                                         const float* __restrict__ B, int ldb,
                                         unsigned long long (&acc)[8][4], int Kd,
                                         int block_m, int block_n) {
    __shared__ float As[2][BK][TILE];
    __shared__ float Bs[2][BK][TILE];

    const int tid = threadIdx.x;
    const int tx = tid & 15;
    const int ty = tid >> 4;

    const int aRow = tid >> 1;
    const int aCol = (tid & 1) * 4;
    const float* Aptr = A + (size_t)(block_m + aRow) * lda + aCol;

    const float* Bptr;
    int bRow, bCol;
    if (BT) {
        bRow = tid >> 1;
        bCol = (tid & 1) * 4;
        Bptr = B + (size_t)(block_n + bRow) * ldb + bCol;
    } else {
        bRow = tid >> 5;
        bCol = (tid & 31) * 4;
        Bptr = B + (size_t)bRow * ldb + block_n + bCol;
    }

    float4 av = *(const float4*)Aptr;
    float4 bv = *(const float4*)Bptr;
    As[0][aCol + 0][aRow] = av.x;
    As[0][aCol + 1][aRow] = av.y;
    As[0][aCol + 2][aRow] = av.z;
    As[0][aCol + 3][aRow] = av.w;
    if (BT) {
        Bs[0][bCol + 0][bRow] = bv.x;
        Bs[0][bCol + 1][bRow] = bv.y;
        Bs[0][bCol + 2][bRow] = bv.z;
        Bs[0][bCol + 3][bRow] = bv.w;
    } else {
        *(float4*)&Bs[0][bRow][bCol] = bv;
    }
    __syncthreads();

    int buf = 0;
#pragma unroll 1
    for (int k0 = 0; k0 < Kd; k0 += BK) {
        const bool hn = (k0 + BK) < Kd;
        if (hn) {
            av = *(const float4*)(Aptr + k0 + BK);
            bv = BT ? *(const float4*)(Bptr + k0 + BK)
                    : *(const float4*)(Bptr + (size_t)(k0 + BK) * ldb);
        }
#pragma unroll
        for (int kk = 0; kk < BK; kk++) {
            const float4 a0 = *(const float4*)&As[buf][kk][ty * 8];
            const float4 a1 = *(const float4*)&As[buf][kk][ty * 8 + 4];
            const ulonglong2 bq0 = *(const ulonglong2*)&Bs[buf][kk][tx * 8];
            const ulonglong2 bq1 = *(const ulonglong2*)&Bs[buf][kk][tx * 8 + 4];
            unsigned long long b2[4] = {bq0.x, bq0.y, bq1.x, bq1.y};
            unsigned long long a2[8] = {dup2(a0.x), dup2(a0.y), dup2(a0.z), dup2(a0.w),
                                        dup2(a1.x), dup2(a1.y), dup2(a1.z), dup2(a1.w)};
#pragma unroll
            for (int i = 0; i < 8; i++)
#pragma unroll
                for (int j = 0; j < 4; j++) ffma2(acc[i][j], a2[i], b2[j]);
        }
        if (hn) {
            const int nb = buf ^ 1;
            As[nb][aCol + 0][aRow] = av.x;
            As[nb][aCol + 1][aRow] = av.y;
            As[nb][aCol + 2][aRow] = av.z;
            As[nb][aCol + 3][aRow] = av.w;
            if (BT) {
                Bs[nb][bCol + 0][bRow] = bv.x;
                Bs[nb][bCol + 1][bRow] = bv.y;
                Bs[nb][bCol + 2][bRow] = bv.z;
                Bs[nb][bCol + 3][bRow] = bv.w;
            } else {
                *(float4*)&Bs[nb][bRow][bCol] = bv;
            }
            __syncthreads();
        }
        buf ^= 1;
    }
}

// ---------------------------------------------------------------------------
// GEMM2 fused: C2 = proj_b[1024,512] @ right_b^T, epilogue tanh+v-dot+softmax
// grid (1, 8, 64), block 256 ; z = br*32 + b
// ---------------------------------------------------------------------------
__global__ __launch_bounds__(256) void k_gemm2(const float* __restrict__ aspect,
                                               const float* __restrict__ polarity,
                                               const float* __restrict__ va,
                                               const float* __restrict__ vp) {
    const int z = blockIdx.z;
    const int br = z >> 5, b = z & 31;
    const float* right = br ? aspect : polarity;
    const float* A = g_proj + (size_t)br * 4096 * 4096 + (size_t)b * 128 * 4096;
    const float* Bm = right + (size_t)b * S_ * H_;
    const int block_m = blockIdx.y * TILE;
    unsigned long long acc[8][4] = {};
    sgemm_db<true>(A, 512, Bm, H_, acc, H_, block_m, 0);

    const float* v = br ? vp : va;
    float vv[8];
#pragma unroll
    for (int i = 0; i < 8; i++) vv[i] = v[i];

    const int tx = threadIdx.x & 15, ty = threadIdx.x >> 4;
    float sc[8] = {0.f, 0.f, 0.f, 0.f, 0.f, 0.f, 0.f, 0.f};
#pragma unroll
    for (int i = 0; i < 8; i++) {
#pragma unroll
        for (int jq = 0; jq < 4; jq++) {
            float2 p = unpack2(acc[i][jq]);
            sc[2 * jq] += vv[i] * tanhf(p.x);
            sc[2 * jq + 1] += vv[i] * tanhf(p.y);
        }
    }

    float m = -1e30f;
#pragma unroll
    for (int j = 0; j < 8; j++) m = fmaxf(m, sc[j]);
#pragma unroll
    for (int o = 8; o; o >>= 1) m = fmaxf(m, __shfl_xor_sync(0xffffffffu, m, o));
    float ssum = 0.f;
#pragma unroll
    for (int j = 0; j < 8; j++) {
        sc[j] = expf(sc[j] - m);
        ssum += sc[j];
    }
#pragma unroll
    for (int o = 8; o; o >>= 1) ssum += __shfl_xor_sync(0xffffffffu, ssum, o);
    const float inv = 1.f / ssum;

    const int srow = (block_m >> 3) + ty;
    float* out = g_attn + (size_t)z * (128 * 128) + (size_t)srow * 128 + tx * 8;
    *(float4*)out = make_float4(sc[0] * inv, sc[1] * inv, sc[2] * inv, sc[3] * inv);
    *(float4*)(out + 4) = make_float4(sc[4] * inv, sc[5] * inv, sc[6] * inv, sc[7] * inv);
}

// ---------------------------------------------------------------------------
// GEMM3: out = bias + attn[128,128] @ values[128,512]
// grid (4, 1, 64), block 256 ; z = br*32 + b
// ---------------------------------------------------------------------------
__global__ __launch_bounds__(256) void k_gemm3(const float* __restrict__ aspect,
                                               const float* __restrict__ polarity,
                                               float* __restrict__ out) {
    const int z = blockIdx.z;
    const int br = z >> 5, b = z & 31;
    const float* A = g_attn + (size_t)z * (128 * 128);
    const float* Bv = (br ? aspect : polarity) + (size_t)b * S_ * H_;
    const float* bias = (br ? polarity : aspect) + (size_t)b * S_ * H_;
    float* C = out + (size_t)br * B_ * S_ * H_ + (size_t)b * S_ * H_;
    const int block_n = blockIdx.x * TILE;
    unsigned long long acc[8][4] = {};
    sgemm_db<false>(A, 128, Bv, H_, acc, 128, 0, block_n);

    const int tx = threadIdx.x & 15, ty = threadIdx.x >> 4;
#pragma unroll
    for (int i = 0; i < 8; i++) {
        const size_t off = (size_t)(ty * 8 + i) * H_ + block_n + tx * 8;
        float4 b0 = *(const float4*)(bias + off);
        float4 b1 = *(const float4*)(bias + off + 4);
        float2 p0 = unpack2(acc[i][0]);
        float2 p1 = unpack2(acc[i][1]);
        float2 p2 = unpack2(acc[i][2]);
        float2 p3 = unpack2(acc[i][3]);
        *(float4*)(C + off) =
            make_float4(b0.x + p0.x, b0.y + p0.y, b0.z + p1.x, b0.w + p1.y);
        *(float4*)(C + off + 4) =
            make_float4(b1.x + p2.x, b1.y + p2.y, b1.z + p3.x, b1.w + p3.y);
    }
}

// ---------------------------------------------------------------------------
extern "C" void kernel_launch(void* const* d_in, const int* in_sizes, int n_in,
                              void* d_out, int out_size) {
    const float* aspect = (const float*)d_in[0];
    const float* polarity = (const float*)d_in[1];
    const float* Gap = (const float*)d_in[2];
    const float* Gpa = (const float*)d_in[3];
    const float* va = (const float*)d_in[4];
    const float* vp = (const float*)d_in[5];
    float* out = (float*)d_out;

    cudaFuncSetAttribute(k_gemm1_mma, cudaFuncAttributeMaxDynamicSharedMemorySize,
                         G1_SMEM_BYTES);

    k_prep_a<<<(4096 * 512 / 4 + 255) / 256, 256>>>(aspect);
    k_prep_g<<<dim3(128, 16, 2), dim3(32, 8)>>>(Gap, Gpa);
    k_gemm1_mma<<<dim3(32, 32, 2), 256, G1_SMEM_BYTES>>>();
    k_gemm2<<<dim3(1, 8, 64), 256>>>(aspect, polarity, va, vp);
    k_gemm3<<<dim3(4, 1, 64), 256>>>(aspect, polarity, out);
}

// round 5
// speedup vs baseline: 2.3393x; 1.8708x over previous
#include <cuda_runtime.h>
#include <cuda_fp16.h>
#include <math.h>
#include <stdint.h>

// Problem constants
#define B_ 32
#define S_ 128
#define H_ 512
#define K_ 8

#define TILE 128
#define BK 8

// Scratch (device globals — no runtime allocation allowed)
__device__ float g_attn[2ull * 32 * 128 * 128];     // softmaxed attention, 4 MB
__device__ __half g_xh[2ull * 32 * 128 * 512];      // inputs fp16-hi (0=aspect,1=polarity)
__device__ __half g_xl[2ull * 32 * 128 * 512];      // inputs fp16-lo
__device__ __half g_gth[2ull * 4096 * 512];         // G^T fp16-hi per branch
__device__ __half g_gtl[2ull * 4096 * 512];         // G^T fp16-lo
__device__ __half g_phi[2ull * 4096 * 4096];        // proj fp16-hi, 64 MB
__device__ __half g_plo[2ull * 4096 * 4096];        // proj fp16-lo, 64 MB

// ===========================================================================
// PTX helpers
// ===========================================================================
__device__ __forceinline__ uint32_t smem_to_u32(const void* p) {
    uint32_t a;
    asm("{ .reg .u64 t; cvta.to.shared.u64 t, %1; cvt.u32.u64 %0, t; }"
        : "=r"(a) : "l"(p));
    return a;
}
__device__ __forceinline__ void cp16(uint32_t s, const void* g) {
    asm volatile(
        "{ .reg .u64 gg; cvta.to.global.u64 gg, %1;"
        "  cp.async.cg.shared.global [%0], [gg], 16; }"
        :: "r"(s), "l"(g));
}
__device__ __forceinline__ void cp_commit() {
    asm volatile("cp.async.commit_group;" ::: "memory");
}
__device__ __forceinline__ void cp_wait0() {
    asm volatile("cp.async.wait_group 0;" ::: "memory");
}
__device__ __forceinline__ void ldsm4(uint32_t& r0, uint32_t& r1, uint32_t& r2,
                                      uint32_t& r3, uint32_t addr) {
    asm volatile("ldmatrix.sync.aligned.m8n8.x4.shared.b16 {%0,%1,%2,%3}, [%4];"
                 : "=r"(r0), "=r"(r1), "=r"(r2), "=r"(r3) : "r"(addr));
}
__device__ __forceinline__ void mma16816(float (&d)[4], const uint32_t (&a)[4],
                                         const uint32_t (&b)[2]) {
    asm volatile(
        "mma.sync.aligned.m16n8k16.row.col.f32.f16.f16.f32 "
        "{%0,%1,%2,%3}, {%4,%5,%6,%7}, {%8,%9}, {%0,%1,%2,%3};"
        : "+f"(d[0]), "+f"(d[1]), "+f"(d[2]), "+f"(d[3])
        : "r"(a[0]), "r"(a[1]), "r"(a[2]), "r"(a[3]), "r"(b[0]), "r"(b[1]));
}
__device__ __forceinline__ void split_h(float x, __half& h, __half& l) {
    h = __float2half_rn(x);
    l = __float2half_rn(x - __half2float(h));
}

// ===========================================================================
// Prep: split inputs (aspect, polarity) into fp16 hi/lo
// ===========================================================================
__global__ __launch_bounds__(256) void k_prep_x(const float* __restrict__ a,
                                                const float* __restrict__ p) {
    const int n4 = 32 * 128 * 512 / 4;
    const int i = blockIdx.x * blockDim.x + threadIdx.x;
    if (i >= 2 * n4) return;
    const int which = i < n4 ? 0 : 1;
    const int j = which ? i - n4 : i;
    float4 v = ((const float4*)(which ? p : a))[j];
    __half h0, l0, h1, l1, h2, l2, h3, l3;
    split_h(v.x, h0, l0);
    split_h(v.y, h1, l1);
    split_h(v.z, h2, l2);
    split_h(v.w, h3, l3);
    const size_t o = (size_t)which * (32 * 128 * 512) + (size_t)j * 4;
    *(__half2*)&g_xh[o] = __halves2half2(h0, h1);
    *(__half2*)&g_xh[o + 2] = __halves2half2(h2, h3);
    *(__half2*)&g_xl[o] = __halves2half2(l0, l1);
    *(__half2*)&g_xl[o + 2] = __halves2half2(l2, l3);
}

// Transpose G[br][512 h, 4096 n] -> GT[br][4096 n, 512 h] as fp16 hi/lo
__global__ __launch_bounds__(256) void k_prep_g(const float* __restrict__ Gap,
                                                const float* __restrict__ Gpa) {
    __shared__ float t[32][33];
    const int br = blockIdx.z;
    const float* G = br ? Gpa : Gap;
    const int n0 = blockIdx.x * 32, k0 = blockIdx.y * 32;
#pragma unroll
    for (int j = 0; j < 4; j++)
        t[threadIdx.y + j * 8][threadIdx.x] =
            G[(size_t)(k0 + threadIdx.y + j * 8) * 4096 + n0 + threadIdx.x];
    __syncthreads();
    __half* GH = g_gth + (size_t)br * 4096 * 512;
    __half* GL = g_gtl + (size_t)br * 4096 * 512;
#pragma unroll
    for (int j = 0; j < 4; j++) {
        const int n = n0 + threadIdx.y + j * 8;
        const int k = k0 + threadIdx.x;
        __half h, l;
        split_h(t[threadIdx.x][threadIdx.y + j * 8], h, l);
        GH[(size_t)n * 512 + k] = h;
        GL[(size_t)n * 512 + k] = l;
    }
}

// ===========================================================================
// GEMM1 (fp16 3x split, mma.sync + ldmatrix, NT):
//   proj[br] = aspect[4096,512] @ GT[br][4096,512]^T  -> fp16 hi/lo
// CTA 128x128, warp tile 32x64 (8 warps), K chunk 16, 2-stage cp.async.
// Smem rows padded to 24 halves (48B) -> LDSM conflict-free.
// ===========================================================================
#define ROWH 24
#define MATH_ (128 * ROWH)      // halves per matrix (3072)
#define MATB (MATH_ * 2)        // 6144 bytes
#define BUFB (4 * MATB)         // 24576 bytes per stage
#define GSMEM (2 * BUFB)        // 49152 bytes

__global__ __launch_bounds__(256) void k_gemm1() {
    extern __shared__ __half sh[];
    const uint32_t sb = smem_to_u32(sh);
    const int tid = threadIdx.x;
    const int wid = tid >> 5, lane = tid & 31;
    const int g = lane >> 2, tig = lane & 3;
    const int sub = lane >> 3, r = lane & 7;
    const int wm = (wid & 3) * 32, wn = (wid >> 2) * 64;

    const int br = blockIdx.z;
    const int m0 = blockIdx.y * 128;
    const int n0 = blockIdx.x * 128;

    const __half* Ah = g_xh + (size_t)m0 * 512;  // aspect rows
    const __half* Al = g_xl + (size_t)m0 * 512;
    const __half* Bh = g_gth + ((size_t)br * 4096 + n0) * 512;
    const __half* Bl = g_gtl + ((size_t)br * 4096 + n0) * 512;

    // ldmatrix lane offsets (bytes, relative to matrix base)
    uint32_t offA[2];
#pragma unroll
    for (int fm = 0; fm < 2; fm++)
        offA[fm] = ((wm + fm * 16 + (sub & 1) * 8 + r) * ROWH + (sub >> 1) * 8) * 2;
    uint32_t offB[4];
#pragma unroll
    for (int p = 0; p < 4; p++)
        offB[p] = ((wn + p * 16 + (sub >> 1) * 8 + r) * ROWH + (sub & 1) * 8) * 2;

    // cp.async mapping: each thread copies one 16B quad per matrix
    const int lrow = tid >> 1, lh = (tid & 1) * 8;
    const uint32_t sdst = (uint32_t)(lrow * ROWH + lh) * 2;

    float acc[2][8][4] = {};

#define G1_LOAD(kc, buf)                                                    \
    {                                                                       \
        const uint32_t bb_ = sb + (buf) * BUFB;                             \
        const size_t so_ = (size_t)lrow * 512 + (kc) * 16 + lh;             \
        cp16(bb_ + 0 * MATB + sdst, Ah + so_);                              \
        cp16(bb_ + 1 * MATB + sdst, Al + so_);                              \
        cp16(bb_ + 2 * MATB + sdst, Bh + so_);                              \
        cp16(bb_ + 3 * MATB + sdst, Bl + so_);                              \
    }

    G1_LOAD(0, 0);
    cp_commit();

#pragma unroll 1
    for (int c = 0; c < 32; c++) {
        cp_wait0();
        __syncthreads();
        const int buf = c & 1;
        if (c < 31) {
            G1_LOAD(c + 1, buf ^ 1);
            cp_commit();
        }
        const uint32_t mb = sb + buf * BUFB;

        uint32_t ah[2][4], al[2][4];
#pragma unroll
        for (int fm = 0; fm < 2; fm++) {
            ldsm4(ah[fm][0], ah[fm][1], ah[fm][2], ah[fm][3], mb + 0 * MATB + offA[fm]);
            ldsm4(al[fm][0], al[fm][1], al[fm][2], al[fm][3], mb + 1 * MATB + offA[fm]);
        }
        uint32_t bh[8][2], bl[8][2];
#pragma unroll
        for (int p = 0; p < 4; p++) {
            ldsm4(bh[2 * p][0], bh[2 * p][1], bh[2 * p + 1][0], bh[2 * p + 1][1],
                  mb + 2 * MATB + offB[p]);
            ldsm4(bl[2 * p][0], bl[2 * p][1], bl[2 * p + 1][0], bl[2 * p + 1][1],
                  mb + 3 * MATB + offB[p]);
        }
#pragma unroll
        for (int fm = 0; fm < 2; fm++)
#pragma unroll
            for (int fn = 0; fn < 8; fn++) {
                mma16816(acc[fm][fn], ah[fm], bh[fn]);
                mma16816(acc[fm][fn], ah[fm], bl[fn]);
                mma16816(acc[fm][fn], al[fm], bh[fn]);
            }
    }

    // Epilogue: split accumulators to fp16 hi/lo, store to g_phi/g_plo
    const size_t cb = (size_t)br * 4096 * 4096;
#pragma unroll
    for (int fm = 0; fm < 2; fm++)
#pragma unroll
        for (int fn = 0; fn < 8; fn++) {
            const int row = m0 + wm + fm * 16 + g;
            const int col = n0 + wn + fn * 8 + tig * 2;
            size_t o = cb + (size_t)row * 4096 + col;
            __half h0, l0, h1, l1;
            split_h(acc[fm][fn][0], h0, l0);
            split_h(acc[fm][fn][1], h1, l1);
            *(__half2*)&g_phi[o] = __halves2half2(h0, h1);
            *(__half2*)&g_plo[o] = __halves2half2(l0, l1);
            o += (size_t)8 * 4096;
            split_h(acc[fm][fn][2], h0, l0);
            split_h(acc[fm][fn][3], h1, l1);
            *(__half2*)&g_phi[o] = __halves2half2(h0, h1);
            *(__half2*)&g_plo[o] = __halves2half2(l0, l1);
        }
}

// ===========================================================================
// GEMM2 fused (fp16 3x split): C2 = proj_b @ right_b^T, epilogue
// tanh + v-dot over k + row softmax -> g_attn (fp32).
// grid (8, 64): x = m-block (128 rows = 16 s), y = z = br*32+b.
// Warp tile 16m x 128n -> softmax fully in-warp.
// ===========================================================================
__global__ __launch_bounds__(256) void k_gemm2(const float* __restrict__ va,
                                               const float* __restrict__ vp) {
    extern __shared__ __half sh[];
    const uint32_t sb = smem_to_u32(sh);
    const int tid = threadIdx.x;
    const int wid = tid >> 5, lane = tid & 31;
    const int g = lane >> 2, tig = lane & 3;
    const int sub = lane >> 3, r = lane & 7;

    const int z = blockIdx.y;
    const int br = z >> 5, b = z & 31;
    const int sB = blockIdx.x * 16;

    const size_t pb = (size_t)br * 4096 * 4096;
    const int rsel = br ? 0 : 1;  // br0: right=polarity, br1: right=aspect
    const __half* Rh = g_xh + (size_t)rsel * (32 * 128 * 512) + (size_t)b * 128 * 512;
    const __half* Rl = g_xl + (size_t)rsel * (32 * 128 * 512) + (size_t)b * 128 * 512;

    // ldmatrix offsets
    const uint32_t offA = ((wid * 16 + (sub & 1) * 8 + r) * ROWH + (sub >> 1) * 8) * 2;
    const uint32_t offB0 = (((sub >> 1) * 8 + r) * ROWH + (sub & 1) * 8) * 2;

    // cp.async mapping
    const int lrow = tid >> 1, lh = (tid & 1) * 8;
    const uint32_t sdst = (uint32_t)(lrow * ROWH + lh) * 2;
    // A source row (s,k) for smem row lrow:
    const size_t arow = ((size_t)(b * 128 + sB + (lrow >> 3))) * 4096 + (lrow & 7) * 512;

    float acc[16][4] = {};

#define G2_LOAD(kc, buf)                                                   \
    {                                                                      \
        const uint32_t bb_ = sb + (buf) * BUFB;                            \
        const size_t ao_ = arow + (kc) * 16 + lh;                          \
        const size_t bo_ = (size_t)lrow * 512 + (kc) * 16 + lh;            \
        cp16(bb_ + 0 * MATB + sdst, g_phi + pb + ao_);                     \
        cp16(bb_ + 1 * MATB + sdst, g_plo + pb + ao_);                     \
        cp16(bb_ + 2 * MATB + sdst, Rh + bo_);                             \
        cp16(bb_ + 3 * MATB + sdst, Rl + bo_);                             \
    }

    G2_LOAD(0, 0);
    cp_commit();

#pragma unroll 1
    for (int c = 0; c < 32; c++) {
        cp_wait0();
        __syncthreads();
        const int buf = c & 1;
        if (c < 31) {
            G2_LOAD(c + 1, buf ^ 1);
            cp_commit();
        }
        const uint32_t mb = sb + buf * BUFB;

        uint32_t ah[4], al[4];
        ldsm4(ah[0], ah[1], ah[2], ah[3], mb + 0 * MATB + offA);
        ldsm4(al[0], al[1], al[2], al[3], mb + 1 * MATB + offA);
#pragma unroll
        for (int p = 0; p < 8; p++) {
            uint32_t b0, b1, b2, b3, c0, c1, c2, c3;
            ldsm4(b0, b1, b2, b3, mb + 2 * MATB + offB0 + p * (16 * ROWH * 2));
            ldsm4(c0, c1, c2, c3, mb + 3 * MATB + offB0 + p * (16 * ROWH * 2));
            {
                uint32_t bh[2] = {b0, b1}, bl2[2] = {c0, c1};
                mma16816(acc[2 * p], ah, bh);
                mma16816(acc[2 * p], ah, bl2);
                mma16816(acc[2 * p], al, bh);
            }
            {
                uint32_t bh[2] = {b2, b3}, bl2[2] = {c2, c3};
                mma16816(acc[2 * p + 1], ah, bh);
                mma16816(acc[2 * p + 1], ah, bl2);
                mma16816(acc[2 * p + 1], al, bh);
            }
        }
    }

    // Epilogue: rows m=g (s0=sB+wid*2, k=g) and m=g+8 (s1=s0+1, k=g)
    const float* vv = br ? vp : va;
    const float vg = vv[g];
    float s0[16][2], s1[16][2];
#pragma unroll
    for (int fn = 0; fn < 16; fn++) {
        s0[fn][0] = vg * tanhf(acc[fn][0]);
        s0[fn][1] = vg * tanhf(acc[fn][1]);
        s1[fn][0] = vg * tanhf(acc[fn][2]);
        s1[fn][1] = vg * tanhf(acc[fn][3]);
    }
    // reduce over k (= over g lane groups): lanes differ by 4,8,16
#pragma unroll
    for (int off = 16; off >= 4; off >>= 1)
#pragma unroll
        for (int fn = 0; fn < 16; fn++) {
            s0[fn][0] += __shfl_xor_sync(0xffffffffu, s0[fn][0], off);
            s0[fn][1] += __shfl_xor_sync(0xffffffffu, s0[fn][1], off);
            s1[fn][0] += __shfl_xor_sync(0xffffffffu, s1[fn][0], off);
            s1[fn][1] += __shfl_xor_sync(0xffffffffu, s1[fn][1], off);
        }
    // softmax over t=128 (16 fn x 2 in-reg, then across tig via xor 1,2)
    float mx0 = -1e30f, mx1 = -1e30f;
#pragma unroll
    for (int fn = 0; fn < 16; fn++) {
        mx0 = fmaxf(mx0, fmaxf(s0[fn][0], s0[fn][1]));
        mx1 = fmaxf(mx1, fmaxf(s1[fn][0], s1[fn][1]));
    }
#pragma unroll
    for (int off = 1; off <= 2; off <<= 1) {
        mx0 = fmaxf(mx0, __shfl_xor_sync(0xffffffffu, mx0, off));
        mx1 = fmaxf(mx1, __shfl_xor_sync(0xffffffffu, mx1, off));
    }
    float sm0 = 0.f, sm1 = 0.f;
#pragma unroll
    for (int fn = 0; fn < 16; fn++) {
        s0[fn][0] = expf(s0[fn][0] - mx0);
        s0[fn][1] = expf(s0[fn][1] - mx0);
        s1[fn][0] = expf(s1[fn][0] - mx1);
        s1[fn][1] = expf(s1[fn][1] - mx1);
        sm0 += s0[fn][0] + s0[fn][1];
        sm1 += s1[fn][0] + s1[fn][1];
    }
#pragma unroll
    for (int off = 1; off <= 2; off <<= 1) {
        sm0 += __shfl_xor_sync(0xffffffffu, sm0, off);
        sm1 += __shfl_xor_sync(0xffffffffu, sm1, off);
    }
    const float inv0 = 1.f / sm0, inv1 = 1.f / sm1;

    if (lane < 4) {  // g == 0 lanes write (others redundant)
        const int si = sB + wid * 2;
        float* d0 = g_attn + (size_t)z * 16384 + (size_t)si * 128;
        float* d1 = d0 + 128;
#pragma unroll
        for (int fn = 0; fn < 16; fn++) {
            *(float2*)&d0[fn * 8 + tig * 2] =
                make_float2(s0[fn][0] * inv0, s0[fn][1] * inv0);
            *(float2*)&d1[fn * 8 + tig * 2] =
                make_float2(s1[fn][0] * inv1, s1[fn][1] * inv1);
        }
    }
}

// ===========================================================================
// FFMA2 helpers + SGEMM body for GEMM3
// ===========================================================================
__device__ __forceinline__ void ffma2(unsigned long long& d, unsigned long long a,
                                      unsigned long long b) {
    asm("fma.rn.f32x2 %0, %1, %2, %0;" : "+l"(d) : "l"(a), "l"(b));
}
__device__ __forceinline__ unsigned long long dup2(float a) {
    unsigned long long r;
    asm("mov.b64 %0, {%1, %1};" : "=l"(r) : "f"(a));
    return r;
}
__device__ __forceinline__ float2 unpack2(unsigned long long v) {
    float2 f;
    asm("mov.b64 {%0, %1}, %2;" : "=f"(f.x), "=f"(f.y) : "l"(v));
    return f;
}

__device__ __forceinline__ void sgemm_nn(const float* __restrict__ A, int lda,
                                         const float* __restrict__ B, int ldb,
                                         unsigned long long (&acc)[8][4], int Kd,
                                         int block_n) {
    __shared__ float As[2][BK][TILE];
    __shared__ float Bs[2][BK][TILE];

    const int tid = threadIdx.x;
    const int tx = tid & 15;
    const int ty = tid >> 4;

    const int aRow = tid >> 1;
    const int aCol = (tid & 1) * 4;
    const float* Aptr = A + (size_t)aRow * lda + aCol;

    const int bRow = tid >> 5;
    const int bCol = (tid & 31) * 4;
    const float* Bptr = B + (size_t)bRow * ldb + block_n + bCol;

    float4 av = *(const float4*)Aptr;
    float4 bv = *(const float4*)Bptr;
    As[0][aCol + 0][aRow] = av.x;
    As[0][aCol + 1][aRow] = av.y;
    As[0][aCol + 2][aRow] = av.z;
    As[0][aCol + 3][aRow] = av.w;
    *(float4*)&Bs[0][bRow][bCol] = bv;
    __syncthreads();

    int buf = 0;
#pragma unroll 1
    for (int k0 = 0; k0 < Kd; k0 += BK) {
        const bool hn = (k0 + BK) < Kd;
        if (hn) {
            av = *(const float4*)(Aptr + k0 + BK);
            bv = *(const float4*)(Bptr + (size_t)(k0 + BK) * ldb);
        }
#pragma unroll
        for (int kk = 0; kk < BK; kk++) {
            const float4 a0 = *(const float4*)&As[buf][kk][ty * 8];
            const float4 a1 = *(const float4*)&As[buf][kk][ty * 8 + 4];
            const ulonglong2 bq0 = *(const ulonglong2*)&Bs[buf][kk][tx * 8];
            const ulonglong2 bq1 = *(const ulonglong2*)&Bs[buf][kk][tx * 8 + 4];
            unsigned long long b2[4] = {bq0.x, bq0.y, bq1.x, bq1.y};
            unsigned long long a2[8] = {dup2(a0.x), dup2(a0.y), dup2(a0.z), dup2(a0.w),
                                        dup2(a1.x), dup2(a1.y), dup2(a1.z), dup2(a1.w)};
#pragma unroll
            for (int i = 0; i < 8; i++)
#pragma unroll
                for (int j = 0; j < 4; j++) ffma2(acc[i][j], a2[i], b2[j]);
        }
        if (hn) {
            const int nb = buf ^ 1;
            As[nb][aCol + 0][aRow] = av.x;
            As[nb][aCol + 1][aRow] = av.y;
            As[nb][aCol + 2][aRow] = av.z;
            As[nb][aCol + 3][aRow] = av.w;
            *(float4*)&Bs[nb][bRow][bCol] = bv;
            __syncthreads();
        }
        buf ^= 1;
    }
}

// GEMM3: out = bias + attn[128,128] @ values[128,512]
__global__ __launch_bounds__(256) void k_gemm3(const float* __restrict__ aspect,
                                               const float* __restrict__ polarity,
                                               float* __restrict__ out) {
    const int z = blockIdx.z;
    const int br = z >> 5, b = z & 31;
    const float* A = g_attn + (size_t)z * (128 * 128);
    const float* Bv = (br ? aspect : polarity) + (size_t)b * S_ * H_;
    const float* bias = (br ? polarity : aspect) + (size_t)b * S_ * H_;
    float* C = out + (size_t)br * B_ * S_ * H_ + (size_t)b * S_ * H_;
    const int block_n = blockIdx.x * TILE;
    unsigned long long acc[8][4] = {};
    sgemm_nn(A, 128, Bv, H_, acc, 128, block_n);

    const int tx = threadIdx.x & 15, ty = threadIdx.x >> 4;
#pragma unroll
    for (int i = 0; i < 8; i++) {
        const size_t off = (size_t)(ty * 8 + i) * H_ + block_n + tx * 8;
        float4 b0 = *(const float4*)(bias + off);
        float4 b1 = *(const float4*)(bias + off + 4);
        float2 p0 = unpack2(acc[i][0]);
        float2 p1 = unpack2(acc[i][1]);
        float2 p2 = unpack2(acc[i][2]);
        float2 p3 = unpack2(acc[i][3]);
        *(float4*)(C + off) =
            make_float4(b0.x + p0.x, b0.y + p0.y, b0.z + p1.x, b0.w + p1.y);
        *(float4*)(C + off + 4) =
            make_float4(b1.x + p2.x, b1.y + p2.y, b1.z + p3.x, b1.w + p3.y);
    }
}

// ---------------------------------------------------------------------------
extern "C" void kernel_launch(void* const* d_in, const int* in_sizes, int n_in,
                              void* d_out, int out_size) {
    const float* aspect = (const float*)d_in[0];
    const float* polarity = (const float*)d_in[1];
    const float* Gap = (const float*)d_in[2];
    const float* Gpa = (const float*)d_in[3];
    const float* va = (const float*)d_in[4];
    const float* vp = (const float*)d_in[5];
    float* out = (float*)d_out;

    cudaFuncSetAttribute(k_gemm1, cudaFuncAttributeMaxDynamicSharedMemorySize, GSMEM);
    cudaFuncSetAttribute(k_gemm2, cudaFuncAttributeMaxDynamicSharedMemorySize, GSMEM);

    k_prep_x<<<(2 * 32 * 128 * 512 / 4 + 255) / 256, 256>>>(aspect, polarity);
    k_prep_g<<<dim3(128, 16, 2), dim3(32, 8)>>>(Gap, Gpa);
    k_gemm1<<<dim3(32, 32, 2), 256, GSMEM>>>();
    k_gemm2<<<dim3(8, 64), 256, GSMEM>>>(va, vp);
    k_gemm3<<<dim3(4, 1, 64), 256>>>(aspect, polarity, out);
}

// round 6
// speedup vs baseline: 2.3516x; 1.0052x over previous
#include <cuda_runtime.h>
#include <cuda_fp16.h>
#include <math.h>
#include <stdint.h>

// Problem constants
#define B_ 32
#define S_ 128
#define H_ 512
#define K_ 8

// Scratch (device globals — no runtime allocation allowed)
__device__ __half g_xh[2ull * 32 * 128 * 512];   // inputs fp16-hi (0=aspect,1=polarity)
__device__ __half g_xl[2ull * 32 * 128 * 512];   // inputs fp16-lo
__device__ __half g_gth[2ull * 4096 * 512];      // G^T fp16-hi per branch
__device__ __half g_gtl[2ull * 4096 * 512];      // G^T fp16-lo
__device__ __half g_phi[2ull * 4096 * 4096];     // proj fp16-hi
__device__ __half g_plo[2ull * 4096 * 4096];     // proj fp16-lo
__device__ __half g_ath[64ull * 128 * 128];      // attn fp16-hi  [z][s][t]
__device__ __half g_atl[64ull * 128 * 128];      // attn fp16-lo
__device__ __half g_vth[2ull * 32 * 512 * 128];  // values^T fp16-hi [which][b][h][t]
__device__ __half g_vtl[2ull * 32 * 512 * 128];  // values^T fp16-lo

// ===========================================================================
// PTX helpers
// ===========================================================================
__device__ __forceinline__ uint32_t smem_to_u32(const void* p) {
    uint32_t a;
    asm("{ .reg .u64 t; cvta.to.shared.u64 t, %1; cvt.u32.u64 %0, t; }"
        : "=r"(a) : "l"(p));
    return a;
}
__device__ __forceinline__ void cp16(uint32_t s, const void* g) {
    asm volatile(
        "{ .reg .u64 gg; cvta.to.global.u64 gg, %1;"
        "  cp.async.cg.shared.global [%0], [gg], 16; }"
        :: "r"(s), "l"(g));
}
__device__ __forceinline__ void cp_commit() {
    asm volatile("cp.async.commit_group;" ::: "memory");
}
__device__ __forceinline__ void cp_wait1() {
    asm volatile("cp.async.wait_group 1;" ::: "memory");
}
__device__ __forceinline__ void ldsm4(uint32_t& r0, uint32_t& r1, uint32_t& r2,
                                      uint32_t& r3, uint32_t addr) {
    asm volatile("ldmatrix.sync.aligned.m8n8.x4.shared.b16 {%0,%1,%2,%3}, [%4];"
                 : "=r"(r0), "=r"(r1), "=r"(r2), "=r"(r3) : "r"(addr));
}
__device__ __forceinline__ void mma16816(float (&d)[4], const uint32_t (&a)[4],
                                         const uint32_t (&b)[2]) {
    asm volatile(
        "mma.sync.aligned.m16n8k16.row.col.f32.f16.f16.f32 "
        "{%0,%1,%2,%3}, {%4,%5,%6,%7}, {%8,%9}, {%0,%1,%2,%3};"
        : "+f"(d[0]), "+f"(d[1]), "+f"(d[2]), "+f"(d[3])
        : "r"(a[0]), "r"(a[1]), "r"(a[2]), "r"(a[3]), "r"(b[0]), "r"(b[1]));
}
__device__ __forceinline__ void split_h(float x, __half& h, __half& l) {
    h = __float2half_rn(x);
    l = __float2half_rn(x - __half2float(h));
}

// ===========================================================================
// Prep kernels
// ===========================================================================
__global__ __launch_bounds__(256) void k_prep_x(const float* __restrict__ a,
                                                const float* __restrict__ p) {
    const int n4 = 32 * 128 * 512 / 4;
    const int i = blockIdx.x * blockDim.x + threadIdx.x;
    if (i >= 2 * n4) return;
    const int which = i < n4 ? 0 : 1;
    const int j = which ? i - n4 : i;
    float4 v = ((const float4*)(which ? p : a))[j];
    __half h0, l0, h1, l1, h2, l2, h3, l3;
    split_h(v.x, h0, l0);
    split_h(v.y, h1, l1);
    split_h(v.z, h2, l2);
    split_h(v.w, h3, l3);
    const size_t o = (size_t)which * (32 * 128 * 512) + (size_t)j * 4;
    *(__half2*)&g_xh[o] = __halves2half2(h0, h1);
    *(__half2*)&g_xh[o + 2] = __halves2half2(h2, h3);
    *(__half2*)&g_xl[o] = __halves2half2(l0, l1);
    *(__half2*)&g_xl[o + 2] = __halves2half2(l2, l3);
}

// Transpose G[br][512 h, 4096 n] -> GT[br][4096 n, 512 h] as fp16 hi/lo
__global__ __launch_bounds__(256) void k_prep_g(const float* __restrict__ Gap,
                                                const float* __restrict__ Gpa) {
    __shared__ float t[32][33];
    const int br = blockIdx.z;
    const float* G = br ? Gpa : Gap;
    const int n0 = blockIdx.x * 32, k0 = blockIdx.y * 32;
#pragma unroll
    for (int j = 0; j < 4; j++)
        t[threadIdx.y + j * 8][threadIdx.x] =
            G[(size_t)(k0 + threadIdx.y + j * 8) * 4096 + n0 + threadIdx.x];
    __syncthreads();
    __half* GH = g_gth + (size_t)br * 4096 * 512;
    __half* GL = g_gtl + (size_t)br * 4096 * 512;
#pragma unroll
    for (int j = 0; j < 4; j++) {
        const int n = n0 + threadIdx.y + j * 8;
        const int k = k0 + threadIdx.x;
        __half h, l;
        split_h(t[threadIdx.x][threadIdx.y + j * 8], h, l);
        GH[(size_t)n * 512 + k] = h;
        GL[(size_t)n * 512 + k] = l;
    }
}

// Transpose inputs x[which][b][128 t, 512 h] -> v^T[which][b][512 h, 128 t] fp16 hi/lo
__global__ __launch_bounds__(256) void k_prep_v(const float* __restrict__ a,
                                                const float* __restrict__ p) {
    __shared__ float t[32][33];
    const int z = blockIdx.z;
    const int which = z >> 5, b = z & 31;
    const float* src = (which ? p : a) + (size_t)b * 128 * 512;
    const int h0 = blockIdx.x * 32, t0 = blockIdx.y * 32;
#pragma unroll
    for (int j = 0; j < 4; j++)
        t[threadIdx.y + j * 8][threadIdx.x] =
            src[(size_t)(t0 + threadIdx.y + j * 8) * 512 + h0 + threadIdx.x];
    __syncthreads();
    __half* VH = g_vth + (size_t)z * 512 * 128;
    __half* VL = g_vtl + (size_t)z * 512 * 128;
#pragma unroll
    for (int j = 0; j < 4; j++) {
        const int h = h0 + threadIdx.y + j * 8;
        const int tt = t0 + threadIdx.x;
        __half hh, ll;
        split_h(t[threadIdx.x][threadIdx.y + j * 8], hh, ll);
        VH[(size_t)h * 128 + tt] = hh;
        VL[(size_t)h * 128 + tt] = ll;
    }
}

// ===========================================================================
// Shared tiling constants (rows padded to 24 halves -> LDSM conflict-free)
// ===========================================================================
#define ROWH 24
#define MATH_ (128 * ROWH)
#define MATB (MATH_ * 2)     // 6144 bytes per matrix tile
#define BUFB (4 * MATB)      // 24576 bytes per stage
#define GSMEM (3 * BUFB)     // 73728 bytes, 3-stage

// ===========================================================================
// GEMM1 (fp16 3x split, NT): proj[br] = aspect[4096,512] @ GT[br]^T
// CTA 128x128, warp 32x64, K chunk 16, 3-stage cp.async.
// ===========================================================================
__global__ __launch_bounds__(256) void k_gemm1() {
    extern __shared__ __half sh[];
    const uint32_t sb = smem_to_u32(sh);
    const int tid = threadIdx.x;
    const int wid = tid >> 5, lane = tid & 31;
    const int g = lane >> 2, tig = lane & 3;
    const int sub = lane >> 3, r = lane & 7;
    const int wm = (wid & 3) * 32, wn = (wid >> 2) * 64;

    const int br = blockIdx.z;
    const int m0 = blockIdx.y * 128;
    const int n0 = blockIdx.x * 128;

    const __half* Ah = g_xh + (size_t)m0 * 512;
    const __half* Al = g_xl + (size_t)m0 * 512;
    const __half* Bh = g_gth + ((size_t)br * 4096 + n0) * 512;
    const __half* Bl = g_gtl + ((size_t)br * 4096 + n0) * 512;

    uint32_t offA[2];
#pragma unroll
    for (int fm = 0; fm < 2; fm++)
        offA[fm] = ((wm + fm * 16 + (sub & 1) * 8 + r) * ROWH + (sub >> 1) * 8) * 2;
    uint32_t offB[4];
#pragma unroll
    for (int p = 0; p < 4; p++)
        offB[p] = ((wn + p * 16 + (sub >> 1) * 8 + r) * ROWH + (sub & 1) * 8) * 2;

    const int lrow = tid >> 1, lh = (tid & 1) * 8;
    const uint32_t sdst = (uint32_t)(lrow * ROWH + lh) * 2;

    float acc[2][8][4] = {};

#define G1_LOAD(kc, buf)                                                    \
    {                                                                       \
        const uint32_t bb_ = sb + (buf) * BUFB;                             \
        const size_t so_ = (size_t)lrow * 512 + (kc) * 16 + lh;             \
        cp16(bb_ + 0 * MATB + sdst, Ah + so_);                              \
        cp16(bb_ + 1 * MATB + sdst, Al + so_);                              \
        cp16(bb_ + 2 * MATB + sdst, Bh + so_);                              \
        cp16(bb_ + 3 * MATB + sdst, Bl + so_);                              \
    }

    G1_LOAD(0, 0);
    cp_commit();
    G1_LOAD(1, 1);
    cp_commit();

#pragma unroll 1
    for (int c = 0; c < 32; c++) {
        cp_wait1();
        __syncthreads();
        const int buf = c % 3;
        if (c + 2 < 32) G1_LOAD(c + 2, (c + 2) % 3);
        cp_commit();
        const uint32_t mb = sb + buf * BUFB;

        uint32_t ah[2][4], al[2][4];
#pragma unroll
        for (int fm = 0; fm < 2; fm++) {
            ldsm4(ah[fm][0], ah[fm][1], ah[fm][2], ah[fm][3], mb + 0 * MATB + offA[fm]);
            ldsm4(al[fm][0], al[fm][1], al[fm][2], al[fm][3], mb + 1 * MATB + offA[fm]);
        }
        uint32_t bh[8][2], bl[8][2];
#pragma unroll
        for (int p = 0; p < 4; p++) {
            ldsm4(bh[2 * p][0], bh[2 * p][1], bh[2 * p + 1][0], bh[2 * p + 1][1],
                  mb + 2 * MATB + offB[p]);
            ldsm4(bl[2 * p][0], bl[2 * p][1], bl[2 * p + 1][0], bl[2 * p + 1][1],
                  mb + 3 * MATB + offB[p]);
        }
#pragma unroll
        for (int fm = 0; fm < 2; fm++)
#pragma unroll
            for (int fn = 0; fn < 8; fn++) {
                mma16816(acc[fm][fn], ah[fm], bh[fn]);
                mma16816(acc[fm][fn], ah[fm], bl[fn]);
                mma16816(acc[fm][fn], al[fm], bh[fn]);
            }
    }

    const size_t cb = (size_t)br * 4096 * 4096;
#pragma unroll
    for (int fm = 0; fm < 2; fm++)
#pragma unroll
        for (int fn = 0; fn < 8; fn++) {
            const int row = m0 + wm + fm * 16 + g;
            const int col = n0 + wn + fn * 8 + tig * 2;
            size_t o = cb + (size_t)row * 4096 + col;
            __half h0, l0, h1, l1;
            split_h(acc[fm][fn][0], h0, l0);
            split_h(acc[fm][fn][1], h1, l1);
            *(__half2*)&g_phi[o] = __halves2half2(h0, h1);
            *(__half2*)&g_plo[o] = __halves2half2(l0, l1);
            o += (size_t)8 * 4096;
            split_h(acc[fm][fn][2], h0, l0);
            split_h(acc[fm][fn][3], h1, l1);
            *(__half2*)&g_phi[o] = __halves2half2(h0, h1);
            *(__half2*)&g_plo[o] = __halves2half2(l0, l1);
        }
}

// ===========================================================================
// GEMM2 fused: C2 = proj_b @ right_b^T, epilogue tanh + v-dot + softmax
// -> attn fp16 hi/lo. grid (8 m-blocks, 64 z), warp tile 16m x 128n.
// ===========================================================================
__global__ __launch_bounds__(256) void k_gemm2(const float* __restrict__ va,
                                               const float* __restrict__ vp) {
    extern __shared__ __half sh[];
    const uint32_t sb = smem_to_u32(sh);
    const int tid = threadIdx.x;
    const int wid = tid >> 5, lane = tid & 31;
    const int g = lane >> 2, tig = lane & 3;
    const int sub = lane >> 3, r = lane & 7;

    const int z = blockIdx.y;
    const int br = z >> 5, b = z & 31;
    const int sB = blockIdx.x * 16;

    const size_t pb = (size_t)br * 4096 * 4096;
    const int rsel = br ? 0 : 1;
    const __half* Rh = g_xh + (size_t)rsel * (32 * 128 * 512) + (size_t)b * 128 * 512;
    const __half* Rl = g_xl + (size_t)rsel * (32 * 128 * 512) + (size_t)b * 128 * 512;

    const uint32_t offA = ((wid * 16 + (sub & 1) * 8 + r) * ROWH + (sub >> 1) * 8) * 2;
    const uint32_t offB0 = (((sub >> 1) * 8 + r) * ROWH + (sub & 1) * 8) * 2;

    const int lrow = tid >> 1, lh = (tid & 1) * 8;
    const uint32_t sdst = (uint32_t)(lrow * ROWH + lh) * 2;
    const size_t arow = ((size_t)(b * 128 + sB + (lrow >> 3))) * 4096 + (lrow & 7) * 512;

    float acc[16][4] = {};

#define G2_LOAD(kc, buf)                                                   \
    {                                                                      \
        const uint32_t bb_ = sb + (buf) * BUFB;                            \
        const size_t ao_ = arow + (kc) * 16 + lh;                          \
        const size_t bo_ = (size_t)lrow * 512 + (kc) * 16 + lh;            \
        cp16(bb_ + 0 * MATB + sdst, g_phi + pb + ao_);                     \
        cp16(bb_ + 1 * MATB + sdst, g_plo + pb + ao_);                     \
        cp16(bb_ + 2 * MATB + sdst, Rh + bo_);                             \
        cp16(bb_ + 3 * MATB + sdst, Rl + bo_);                             \
    }

    G2_LOAD(0, 0);
    cp_commit();
    G2_LOAD(1, 1);
    cp_commit();

#pragma unroll 1
    for (int c = 0; c < 32; c++) {
        cp_wait1();
        __syncthreads();
        const int buf = c % 3;
        if (c + 2 < 32) G2_LOAD(c + 2, (c + 2) % 3);
        cp_commit();
        const uint32_t mb = sb + buf * BUFB;

        uint32_t ah[4], al[4];
        ldsm4(ah[0], ah[1], ah[2], ah[3], mb + 0 * MATB + offA);
        ldsm4(al[0], al[1], al[2], al[3], mb + 1 * MATB + offA);
#pragma unroll
        for (int p = 0; p < 8; p++) {
            uint32_t b0, b1, b2, b3, c0, c1, c2, c3;
            ldsm4(b0, b1, b2, b3, mb + 2 * MATB + offB0 + p * (16 * ROWH * 2));
            ldsm4(c0, c1, c2, c3, mb + 3 * MATB + offB0 + p * (16 * ROWH * 2));
            {
                uint32_t bh[2] = {b0, b1}, bl2[2] = {c0, c1};
                mma16816(acc[2 * p], ah, bh);
                mma16816(acc[2 * p], ah, bl2);
                mma16816(acc[2 * p], al, bh);
            }
            {
                uint32_t bh[2] = {b2, b3}, bl2[2] = {c2, c3};
                mma16816(acc[2 * p + 1], ah, bh);
                mma16816(acc[2 * p + 1], ah, bl2);
                mma16816(acc[2 * p + 1], al, bh);
            }
        }
    }

    const float* vv = br ? vp : va;
    const float vg = vv[g];
    float s0[16][2], s1[16][2];
#pragma unroll
    for (int fn = 0; fn < 16; fn++) {
        s0[fn][0] = vg * tanhf(acc[fn][0]);
        s0[fn][1] = vg * tanhf(acc[fn][1]);
        s1[fn][0] = vg * tanhf(acc[fn][2]);
        s1[fn][1] = vg * tanhf(acc[fn][3]);
    }
#pragma unroll
    for (int off = 16; off >= 4; off >>= 1)
#pragma unroll
        for (int fn = 0; fn < 16; fn++) {
            s0[fn][0] += __shfl_xor_sync(0xffffffffu, s0[fn][0], off);
            s0[fn][1] += __shfl_xor_sync(0xffffffffu, s0[fn][1], off);
            s1[fn][0] += __shfl_xor_sync(0xffffffffu, s1[fn][0], off);
            s1[fn][1] += __shfl_xor_sync(0xffffffffu, s1[fn][1], off);
        }
    float mx0 = -1e30f, mx1 = -1e30f;
#pragma unroll
    for (int fn = 0; fn < 16; fn++) {
        mx0 = fmaxf(mx0, fmaxf(s0[fn][0], s0[fn][1]));
        mx1 = fmaxf(mx1, fmaxf(s1[fn][0], s1[fn][1]));
    }
#pragma unroll
    for (int off = 1; off <= 2; off <<= 1) {
        mx0 = fmaxf(mx0, __shfl_xor_sync(0xffffffffu, mx0, off));
        mx1 = fmaxf(mx1, __shfl_xor_sync(0xffffffffu, mx1, off));
    }
    float sm0 = 0.f, sm1 = 0.f;
#pragma unroll
    for (int fn = 0; fn < 16; fn++) {
        s0[fn][0] = expf(s0[fn][0] - mx0);
        s0[fn][1] = expf(s0[fn][1] - mx0);
        s1[fn][0] = expf(s1[fn][0] - mx1);
        s1[fn][1] = expf(s1[fn][1] - mx1);
        sm0 += s0[fn][0] + s0[fn][1];
        sm1 += s1[fn][0] + s1[fn][1];
    }
#pragma unroll
    for (int off = 1; off <= 2; off <<= 1) {
        sm0 += __shfl_xor_sync(0xffffffffu, sm0, off);
        sm1 += __shfl_xor_sync(0xffffffffu, sm1, off);
    }
    const float inv0 = 1.f / sm0, inv1 = 1.f / sm1;

    if (lane < 4) {
        const int si = sB + wid * 2;
        const size_t base0 = (size_t)z * 16384 + (size_t)si * 128;
        const size_t base1 = base0 + 128;
#pragma unroll
        for (int fn = 0; fn < 16; fn++) {
            __half h0, l0, h1, l1;
            split_h(s0[fn][0] * inv0, h0, l0);
            split_h(s0[fn][1] * inv0, h1, l1);
            *(__half2*)&g_ath[base0 + fn * 8 + tig * 2] = __halves2half2(h0, h1);
            *(__half2*)&g_atl[base0 + fn * 8 + tig * 2] = __halves2half2(l0, l1);
            split_h(s1[fn][0] * inv1, h0, l0);
            split_h(s1[fn][1] * inv1, h1, l1);
            *(__half2*)&g_ath[base1 + fn * 8 + tig * 2] = __halves2half2(h0, h1);
            *(__half2*)&g_atl[base1 + fn * 8 + tig * 2] = __halves2half2(l0, l1);
        }
    }
}

// ===========================================================================
// GEMM3 (fp16 3x split, NT): out = bias + attn[128,128] @ V^T[512,128]^T
// grid (4 h-blocks, 64 z), CTA 128x128, K = t = 128 (8 chunks).
// ===========================================================================
__global__ __launch_bounds__(256) void k_gemm3(const float* __restrict__ aspect,
                                               const float* __restrict__ polarity,
                                               float* __restrict__ out) {
    extern __shared__ __half sh[];
    const uint32_t sb = smem_to_u32(sh);
    const int tid = threadIdx.x;
    const int wid = tid >> 5, lane = tid & 31;
    const int g = lane >> 2, tig = lane & 3;
    const int sub = lane >> 3, r = lane & 7;
    const int wm = (wid & 3) * 32, wn = (wid >> 2) * 64;

    const int z = blockIdx.y;
    const int br = z >> 5, b = z & 31;
    const int h0 = blockIdx.x * 128;

    const int vsel = br ? 0 : 1;  // br0 values = polarity, br1 = aspect
    const __half* Ah = g_ath + (size_t)z * 16384;
    const __half* Al = g_atl + (size_t)z * 16384;
    const __half* Bh = g_vth + ((size_t)(vsel * 32 + b) * 512 + h0) * 128;
    const __half* Bl = g_vtl + ((size_t)(vsel * 32 + b) * 512 + h0) * 128;

    uint32_t offA[2];
#pragma unroll
    for (int fm = 0; fm < 2; fm++)
        offA[fm] = ((wm + fm * 16 + (sub & 1) * 8 + r) * ROWH + (sub >> 1) * 8) * 2;
    uint32_t offB[4];
#pragma unroll
    for (int p = 0; p < 4; p++)
        offB[p] = ((wn + p * 16 + (sub >> 1) * 8 + r) * ROWH + (sub & 1) * 8) * 2;

    const int lrow = tid >> 1, lh = (tid & 1) * 8;
    const uint32_t sdst = (uint32_t)(lrow * ROWH + lh) * 2;

    float acc[2][8][4] = {};

#define G3_LOAD(kc, buf)                                                    \
    {                                                                       \
        const uint32_t bb_ = sb + (buf) * BUFB;                             \
        const size_t so_ = (size_t)lrow * 128 + (kc) * 16 + lh;             \
        cp16(bb_ + 0 * MATB + sdst, Ah + so_);                              \
        cp16(bb_ + 1 * MATB + sdst, Al + so_);                              \
        cp16(bb_ + 2 * MATB + sdst, Bh + so_);                              \
        cp16(bb_ + 3 * MATB + sdst, Bl + so_);                              \
    }

    G3_LOAD(0, 0);
    cp_commit();
    G3_LOAD(1, 1);
    cp_commit();

#pragma unroll 1
    for (int c = 0; c < 8; c++) {
        cp_wait1();
        __syncthreads();
        const int buf = c % 3;
        if (c + 2 < 8) G3_LOAD(c + 2, (c + 2) % 3);
        cp_commit();
        const uint32_t mb = sb + buf * BUFB;

        uint32_t ah[2][4], al[2][4];
#pragma unroll
        for (int fm = 0; fm < 2; fm++) {
            ldsm4(ah[fm][0], ah[fm][1], ah[fm][2], ah[fm][3], mb + 0 * MATB + offA[fm]);
            ldsm4(al[fm][0], al[fm][1], al[fm][2], al[fm][3], mb + 1 * MATB + offA[fm]);
        }
        uint32_t bh[8][2], bl[8][2];
#pragma unroll
        for (int p = 0; p < 4; p++) {
            ldsm4(bh[2 * p][0], bh[2 * p][1], bh[2 * p + 1][0], bh[2 * p + 1][1],
                  mb + 2 * MATB + offB[p]);
            ldsm4(bl[2 * p][0], bl[2 * p][1], bl[2 * p + 1][0], bl[2 * p + 1][1],
                  mb + 3 * MATB + offB[p]);
        }
#pragma unroll
        for (int fm = 0; fm < 2; fm++)
#pragma unroll
            for (int fn = 0; fn < 8; fn++) {
                mma16816(acc[fm][fn], ah[fm], bh[fn]);
                mma16816(acc[fm][fn], ah[fm], bl[fn]);
                mma16816(acc[fm][fn], al[fm], bh[fn]);
            }
    }

    const float* bias = (br ? polarity : aspect) + (size_t)b * 128 * 512;
    float* C = out + (size_t)br * (32 * 128 * 512) + (size_t)b * 128 * 512;
#pragma unroll
    for (int fm = 0; fm < 2; fm++)
#pragma unroll
        for (int fn = 0; fn < 8; fn++) {
            const int row = wm + fm * 16 + g;
            const int col = h0 + wn + fn * 8 + tig * 2;
            size_t o = (size_t)row * 512 + col;
            float2 bv = *(const float2*)&bias[o];
            *(float2*)&C[o] =
                make_float2(bv.x + acc[fm][fn][0], bv.y + acc[fm][fn][1]);
            o += (size_t)8 * 512;
            bv = *(const float2*)&bias[o];
            *(float2*)&C[o] =
                make_float2(bv.x + acc[fm][fn][2], bv.y + acc[fm][fn][3]);
        }
}

// ---------------------------------------------------------------------------
extern "C" void kernel_launch(void* const* d_in, const int* in_sizes, int n_in,
                              void* d_out, int out_size) {
    const float* aspect = (const float*)d_in[0];
    const float* polarity = (const float*)d_in[1];
    const float* Gap = (const float*)d_in[2];
    const float* Gpa = (const float*)d_in[3];
    const float* va = (const float*)d_in[4];
    const float* vp = (const float*)d_in[5];
    float* out = (float*)d_out;

    cudaFuncSetAttribute(k_gemm1, cudaFuncAttributeMaxDynamicSharedMemorySize, GSMEM);
    cudaFuncSetAttribute(k_gemm2, cudaFuncAttributeMaxDynamicSharedMemorySize, GSMEM);
    cudaFuncSetAttribute(k_gemm3, cudaFuncAttributeMaxDynamicSharedMemorySize, GSMEM);

    k_prep_x<<<(2 * 32 * 128 * 512 / 4 + 255) / 256, 256>>>(aspect, polarity);
    k_prep_g<<<dim3(128, 16, 2), dim3(32, 8)>>>(Gap, Gpa);
    k_prep_v<<<dim3(16, 4, 64), dim3(32, 8)>>>(aspect, polarity);
    k_gemm1<<<dim3(32, 32, 2), 256, GSMEM>>>();
    k_gemm2<<<dim3(8, 64), 256, GSMEM>>>(va, vp);
    k_gemm3<<<dim3(4, 64), 256, GSMEM>>>(aspect, polarity, out);
}

// round 7
// speedup vs baseline: 2.5117x; 1.0681x over previous
#include <cuda_runtime.h>
#include <cuda_fp16.h>
#include <math.h>
#include <stdint.h>

// Problem constants
#define B_ 32
#define S_ 128
#define H_ 512
#define K_ 8

// Scratch (device globals — no runtime allocation allowed)
__device__ __half g_xh[2ull * 32 * 128 * 512];   // inputs fp16-hi (0=aspect,1=polarity)
__device__ __half g_xl[2ull * 32 * 128 * 512];   // inputs fp16-lo
__device__ __half g_gth[2ull * 4096 * 512];      // G^T fp16-hi per branch
__device__ __half g_gtl[2ull * 4096 * 512];      // G^T fp16-lo
__device__ __half g_phi[2ull * 4096 * 4096];     // proj fp16-hi
__device__ __half g_plo[2ull * 4096 * 4096];     // proj fp16-lo
__device__ __half g_ath[64ull * 128 * 128];      // attn fp16-hi  [z][s][t]
__device__ __half g_atl[64ull * 128 * 128];      // attn fp16-lo
__device__ __half g_vth[2ull * 32 * 512 * 128];  // values^T fp16-hi [which][b][h][t]
__device__ __half g_vtl[2ull * 32 * 512 * 128];  // values^T fp16-lo

// ===========================================================================
// PTX helpers
// ===========================================================================
__device__ __forceinline__ uint32_t smem_to_u32(const void* p) {
    uint32_t a;
    asm("{ .reg .u64 t; cvta.to.shared.u64 t, %1; cvt.u32.u64 %0, t; }"
        : "=r"(a) : "l"(p));
    return a;
}
__device__ __forceinline__ void cp16(uint32_t s, const void* g) {
    asm volatile(
        "{ .reg .u64 gg; cvta.to.global.u64 gg, %1;"
        "  cp.async.cg.shared.global [%0], [gg], 16; }"
        :: "r"(s), "l"(g));
}
__device__ __forceinline__ void cp_commit() {
    asm volatile("cp.async.commit_group;" ::: "memory");
}
__device__ __forceinline__ void cp_wait1() {
    asm volatile("cp.async.wait_group 1;" ::: "memory");
}
__device__ __forceinline__ void ldsm4(uint32_t& r0, uint32_t& r1, uint32_t& r2,
                                      uint32_t& r3, uint32_t addr) {
    asm volatile("ldmatrix.sync.aligned.m8n8.x4.shared.b16 {%0,%1,%2,%3}, [%4];"
                 : "=r"(r0), "=r"(r1), "=r"(r2), "=r"(r3) : "r"(addr));
}
__device__ __forceinline__ void mma16816(float (&d)[4], const uint32_t (&a)[4],
                                         const uint32_t (&b)[2]) {
    asm volatile(
        "mma.sync.aligned.m16n8k16.row.col.f32.f16.f16.f32 "
        "{%0,%1,%2,%3}, {%4,%5,%6,%7}, {%8,%9}, {%0,%1,%2,%3};"
        : "+f"(d[0]), "+f"(d[1]), "+f"(d[2]), "+f"(d[3])
        : "r"(a[0]), "r"(a[1]), "r"(a[2]), "r"(a[3]), "r"(b[0]), "r"(b[1]));
}
__device__ __forceinline__ void split_h(float x, __half& h, __half& l) {
    h = __float2half_rn(x);
    l = __float2half_rn(x - __half2float(h));
}

// ===========================================================================
// Prep kernels
// ===========================================================================
__global__ __launch_bounds__(256) void k_prep_x(const float* __restrict__ a,
                                                const float* __restrict__ p) {
    const int n4 = 32 * 128 * 512 / 4;
    const int i = blockIdx.x * blockDim.x + threadIdx.x;
    if (i >= 2 * n4) return;
    const int which = i < n4 ? 0 : 1;
    const int j = which ? i - n4 : i;
    float4 v = ((const float4*)(which ? p : a))[j];
    __half h0, l0, h1, l1, h2, l2, h3, l3;
    split_h(v.x, h0, l0);
    split_h(v.y, h1, l1);
    split_h(v.z, h2, l2);
    split_h(v.w, h3, l3);
    const size_t o = (size_t)which * (32 * 128 * 512) + (size_t)j * 4;
    *(__half2*)&g_xh[o] = __halves2half2(h0, h1);
    *(__half2*)&g_xh[o + 2] = __halves2half2(h2, h3);
    *(__half2*)&g_xl[o] = __halves2half2(l0, l1);
    *(__half2*)&g_xl[o + 2] = __halves2half2(l2, l3);
}

// Transpose G[br][512 h, 4096 n] -> GT[br][4096 n, 512 h] as fp16 hi/lo
__global__ __launch_bounds__(256) void k_prep_g(const float* __restrict__ Gap,
                                                const float* __restrict__ Gpa) {
    __shared__ float t[32][33];
    const int br = blockIdx.z;
    const float* G = br ? Gpa : Gap;
    const int n0 = blockIdx.x * 32, k0 = blockIdx.y * 32;
#pragma unroll
    for (int j = 0; j < 4; j++)
        t[threadIdx.y + j * 8][threadIdx.x] =
            G[(size_t)(k0 + threadIdx.y + j * 8) * 4096 + n0 + threadIdx.x];
    __syncthreads();
    __half* GH = g_gth + (size_t)br * 4096 * 512;
    __half* GL = g_gtl + (size_t)br * 4096 * 512;
#pragma unroll
    for (int j = 0; j < 4; j++) {
        const int n = n0 + threadIdx.y + j * 8;
        const int k = k0 + threadIdx.x;
        __half h, l;
        split_h(t[threadIdx.x][threadIdx.y + j * 8], h, l);
        GH[(size_t)n * 512 + k] = h;
        GL[(size_t)n * 512 + k] = l;
    }
}

// Transpose inputs x[which][b][128 t, 512 h] -> v^T[which][b][512 h, 128 t]
__global__ __launch_bounds__(256) void k_prep_v(const float* __restrict__ a,
                                                const float* __restrict__ p) {
    __shared__ float t[32][33];
    const int z = blockIdx.z;
    const int which = z >> 5, b = z & 31;
    const float* src = (which ? p : a) + (size_t)b * 128 * 512;
    const int h0 = blockIdx.x * 32, t0 = blockIdx.y * 32;
#pragma unroll
    for (int j = 0; j < 4; j++)
        t[threadIdx.y + j * 8][threadIdx.x] =
            src[(size_t)(t0 + threadIdx.y + j * 8) * 512 + h0 + threadIdx.x];
    __syncthreads();
    __half* VH = g_vth + (size_t)z * 512 * 128;
    __half* VL = g_vtl + (size_t)z * 512 * 128;
#pragma unroll
    for (int j = 0; j < 4; j++) {
        const int h = h0 + threadIdx.y + j * 8;
        const int tt = t0 + threadIdx.x;
        __half hh, ll;
        split_h(t[threadIdx.x][threadIdx.y + j * 8], hh, ll);
        VH[(size_t)h * 128 + tt] = hh;
        VL[(size_t)h * 128 + tt] = ll;
    }
}

// ===========================================================================
// Shared tiling constants (rows padded to 24 halves -> LDSM conflict-free)
// ===========================================================================
#define ROWH 24
#define MATH_ (128 * ROWH)
#define MATB (MATH_ * 2)     // 6144 bytes per matrix tile
#define BUFB (4 * MATB)      // 24576 bytes per stage
#define GSMEM (3 * BUFB)     // 73728 bytes, 3-stage

// ===========================================================================
// GEMM1 (fp16 3x split, NT): proj[br] = aspect[4096,512] @ GT[br]^T
// 512 threads, CTA 128x128, warp tile 32x32 (4x4 warps), K chunk 16, 3-stage.
// ===========================================================================
__global__ __launch_bounds__(512) void k_gemm1() {
    extern __shared__ __half sh[];
    const uint32_t sb = smem_to_u32(sh);
    const int tid = threadIdx.x;
    const int wid = tid >> 5, lane = tid & 31;
    const int g = lane >> 2, tig = lane & 3;
    const int sub = lane >> 3, r = lane & 7;
    const int wm = (wid & 3) * 32, wn = (wid >> 2) * 32;

    const int br = blockIdx.z;
    const int m0 = blockIdx.y * 128;
    const int n0 = blockIdx.x * 128;

    const __half* Ah = g_xh + (size_t)m0 * 512;
    const __half* Al = g_xl + (size_t)m0 * 512;
    const __half* Bh = g_gth + ((size_t)br * 4096 + n0) * 512;
    const __half* Bl = g_gtl + ((size_t)br * 4096 + n0) * 512;

    uint32_t offA[2], offB[2];
#pragma unroll
    for (int fm = 0; fm < 2; fm++)
        offA[fm] = ((wm + fm * 16 + (sub & 1) * 8 + r) * ROWH + (sub >> 1) * 8) * 2;
#pragma unroll
    for (int p = 0; p < 2; p++)
        offB[p] = ((wn + p * 16 + (sub >> 1) * 8 + r) * ROWH + (sub & 1) * 8) * 2;

    // Loader: 512 threads, 2 cp16 each. tid>>8 selects hi(0)/lo(1) matrices.
    const int hl = tid >> 8;
    const int w = tid & 255;
    const int lrow = w >> 1, lcol = (w & 1) * 8;
    const uint32_t sdst = (uint32_t)(lrow * ROWH + lcol) * 2;
    const __half* PA = hl ? Al : Ah;
    const __half* PB = hl ? Bl : Bh;
    const uint32_t dA = hl * MATB, dB = (2 + hl) * MATB;

    float acc[2][4][4] = {};

#define G1_LOAD(kc, buf)                                              \
    {                                                                 \
        const uint32_t bb_ = sb + (buf) * BUFB;                       \
        const size_t so_ = (size_t)lrow * 512 + (kc) * 16 + lcol;     \
        cp16(bb_ + dA + sdst, PA + so_);                              \
        cp16(bb_ + dB + sdst, PB + so_);                              \
    }

    G1_LOAD(0, 0);
    cp_commit();
    G1_LOAD(1, 1);
    cp_commit();

#pragma unroll 1
    for (int c = 0; c < 32; c++) {
        cp_wait1();
        __syncthreads();
        const int buf = c % 3;
        if (c + 2 < 32) G1_LOAD(c + 2, (c + 2) % 3);
        cp_commit();
        const uint32_t mb = sb + buf * BUFB;

        uint32_t ah[2][4], al[2][4];
#pragma unroll
        for (int fm = 0; fm < 2; fm++) {
            ldsm4(ah[fm][0], ah[fm][1], ah[fm][2], ah[fm][3], mb + 0 * MATB + offA[fm]);
            ldsm4(al[fm][0], al[fm][1], al[fm][2], al[fm][3], mb + 1 * MATB + offA[fm]);
        }
        uint32_t bh[4][2], bl[4][2];
#pragma unroll
        for (int p = 0; p < 2; p++) {
            ldsm4(bh[2 * p][0], bh[2 * p][1], bh[2 * p + 1][0], bh[2 * p + 1][1],
                  mb + 2 * MATB + offB[p]);
            ldsm4(bl[2 * p][0], bl[2 * p][1], bl[2 * p + 1][0], bl[2 * p + 1][1],
                  mb + 3 * MATB + offB[p]);
        }
#pragma unroll
        for (int fm = 0; fm < 2; fm++)
#pragma unroll
            for (int fn = 0; fn < 4; fn++) {
                mma16816(acc[fm][fn], ah[fm], bh[fn]);
                mma16816(acc[fm][fn], ah[fm], bl[fn]);
                mma16816(acc[fm][fn], al[fm], bh[fn]);
            }
    }

    const size_t cb = (size_t)br * 4096 * 4096;
#pragma unroll
    for (int fm = 0; fm < 2; fm++)
#pragma unroll
        for (int fn = 0; fn < 4; fn++) {
            const int row = m0 + wm + fm * 16 + g;
            const int col = n0 + wn + fn * 8 + tig * 2;
            size_t o = cb + (size_t)row * 4096 + col;
            __half h0, l0, h1, l1;
            split_h(acc[fm][fn][0], h0, l0);
            split_h(acc[fm][fn][1], h1, l1);
            *(__half2*)&g_phi[o] = __halves2half2(h0, h1);
            *(__half2*)&g_plo[o] = __halves2half2(l0, l1);
            o += (size_t)8 * 4096;
            split_h(acc[fm][fn][2], h0, l0);
            split_h(acc[fm][fn][3], h1, l1);
            *(__half2*)&g_phi[o] = __halves2half2(h0, h1);
            *(__half2*)&g_plo[o] = __halves2half2(l0, l1);
        }
}

// ===========================================================================
// GEMM2 fused (512 thr, warp 32x32): C2 = proj_b @ right_b^T; epilogue
// tanh + v-dot (k = g per lane) + block softmax -> attn fp16 hi/lo.
// grid (8 m-blocks, 64 z). CTA m tile = 128 rows = 16 s x 8 k.
// ===========================================================================
__global__ __launch_bounds__(512) void k_gemm2(const float* __restrict__ va,
                                               const float* __restrict__ vp) {
    extern __shared__ __half sh[];
    const uint32_t sb = smem_to_u32(sh);
    float* sc = (float*)sh;  // reused after mainloop: [16][132]
    const int tid = threadIdx.x;
    const int wid = tid >> 5, lane = tid & 31;
    const int g = lane >> 2, tig = lane & 3;
    const int sub = lane >> 3, r = lane & 7;
    const int wm = (wid & 3) * 32, wn = (wid >> 2) * 32;

    const int z = blockIdx.y;
    const int br = z >> 5, b = z & 31;
    const int sB = blockIdx.x * 16;

    const size_t pb = (size_t)br * 4096 * 4096;
    const int rsel = br ? 0 : 1;
    const __half* Rh = g_xh + (size_t)rsel * (32 * 128 * 512) + (size_t)b * 128 * 512;
    const __half* Rl = g_xl + (size_t)rsel * (32 * 128 * 512) + (size_t)b * 128 * 512;

    uint32_t offA[2], offB[2];
#pragma unroll
    for (int fm = 0; fm < 2; fm++)
        offA[fm] = ((wm + fm * 16 + (sub & 1) * 8 + r) * ROWH + (sub >> 1) * 8) * 2;
#pragma unroll
    for (int p = 0; p < 2; p++)
        offB[p] = ((wn + p * 16 + (sub >> 1) * 8 + r) * ROWH + (sub & 1) * 8) * 2;

    const int hl = tid >> 8;
    const int w = tid & 255;
    const int lrow = w >> 1, lcol = (w & 1) * 8;
    const uint32_t sdst = (uint32_t)(lrow * ROWH + lcol) * 2;
    const __half* PA =
        (hl ? g_plo : g_phi) + pb +
        ((size_t)(b * 128 + sB + (lrow >> 3))) * 4096 + (size_t)(lrow & 7) * 512;
    const __half* PB = (hl ? Rl : Rh) + (size_t)lrow * 512;
    const uint32_t dA = hl * MATB, dB = (2 + hl) * MATB;

    float acc[2][4][4] = {};

#define G2_LOAD(kc, buf)                                              \
    {                                                                 \
        const uint32_t bb_ = sb + (buf) * BUFB;                       \
        cp16(bb_ + dA + sdst, PA + (kc) * 16 + lcol);                 \
        cp16(bb_ + dB + sdst, PB + (kc) * 16 + lcol);                 \
    }

    G2_LOAD(0, 0);
    cp_commit();
    G2_LOAD(1, 1);
    cp_commit();

#pragma unroll 1
    for (int c = 0; c < 32; c++) {
        cp_wait1();
        __syncthreads();
        const int buf = c % 3;
        if (c + 2 < 32) G2_LOAD(c + 2, (c + 2) % 3);
        cp_commit();
        const uint32_t mb = sb + buf * BUFB;

        uint32_t ah[2][4], al[2][4];
#pragma unroll
        for (int fm = 0; fm < 2; fm++) {
            ldsm4(ah[fm][0], ah[fm][1], ah[fm][2], ah[fm][3], mb + 0 * MATB + offA[fm]);
            ldsm4(al[fm][0], al[fm][1], al[fm][2], al[fm][3], mb + 1 * MATB + offA[fm]);
        }
        uint32_t bh[4][2], bl[4][2];
#pragma unroll
        for (int p = 0; p < 2; p++) {
            ldsm4(bh[2 * p][0], bh[2 * p][1], bh[2 * p + 1][0], bh[2 * p + 1][1],
                  mb + 2 * MATB + offB[p]);
            ldsm4(bl[2 * p][0], bl[2 * p][1], bl[2 * p + 1][0], bl[2 * p + 1][1],
                  mb + 3 * MATB + offB[p]);
        }
#pragma unroll
        for (int fm = 0; fm < 2; fm++)
#pragma unroll
            for (int fn = 0; fn < 4; fn++) {
                mma16816(acc[fm][fn], ah[fm], bh[fn]);
                mma16816(acc[fm][fn], ah[fm], bl[fn]);
                mma16816(acc[fm][fn], al[fm], bh[fn]);
            }
    }

    // Epilogue part 1: per-lane k = g for all 4 rows; tanh, weight by v[g],
    // reduce over k via shfl (offsets 4,8,16).
    const float* vv = br ? vp : va;
    const float vg = vv[g];
    float red[4][4][2];  // [s_idx][fn][col pair]
#pragma unroll
    for (int fm = 0; fm < 2; fm++)
#pragma unroll
        for (int fn = 0; fn < 4; fn++) {
            red[fm * 2 + 0][fn][0] = vg * tanhf(acc[fm][fn][0]);
            red[fm * 2 + 0][fn][1] = vg * tanhf(acc[fm][fn][1]);
            red[fm * 2 + 1][fn][0] = vg * tanhf(acc[fm][fn][2]);
            red[fm * 2 + 1][fn][1] = vg * tanhf(acc[fm][fn][3]);
        }
#pragma unroll
    for (int off = 16; off >= 4; off >>= 1)
#pragma unroll
        for (int si = 0; si < 4; si++)
#pragma unroll
            for (int fn = 0; fn < 4; fn++) {
                red[si][fn][0] += __shfl_xor_sync(0xffffffffu, red[si][fn][0], off);
                red[si][fn][1] += __shfl_xor_sync(0xffffffffu, red[si][fn][1], off);
            }

    __syncthreads();  // mainloop smem dead; reuse as score tile
    if (g == 0) {
        // s rows: warp covers s = (wid&3)*4 + si ; cols wn + fn*8 + tig*2
#pragma unroll
        for (int si = 0; si < 4; si++) {
            const int srow = (wid & 3) * 4 + si;
#pragma unroll
            for (int fn = 0; fn < 4; fn++) {
                sc[srow * 132 + wn + fn * 8 + tig * 2] = red[si][fn][0];
                sc[srow * 132 + wn + fn * 8 + tig * 2 + 1] = red[si][fn][1];
            }
        }
    }
    __syncthreads();

    // Epilogue part 2: softmax over t=128 per s row, write fp16 hi/lo attn.
    if (tid < 256) {
        const int row = tid >> 4, l16 = tid & 15;
        float vals[8];
        float mx = -1e30f;
#pragma unroll
        for (int i = 0; i < 8; i++) {
            vals[i] = sc[row * 132 + l16 * 8 + i];
            mx = fmaxf(mx, vals[i]);
        }
#pragma unroll
        for (int off = 1; off <= 8; off <<= 1)
            mx = fmaxf(mx, __shfl_xor_sync(0xffffffffu, mx, off));
        float sm = 0.f;
#pragma unroll
        for (int i = 0; i < 8; i++) {
            vals[i] = expf(vals[i] - mx);
            sm += vals[i];
        }
#pragma unroll
        for (int off = 1; off <= 8; off <<= 1)
            sm += __shfl_xor_sync(0xffffffffu, sm, off);
        const float inv = 1.f / sm;
        const size_t base = (size_t)z * 16384 + (size_t)(sB + row) * 128 + l16 * 8;
#pragma unroll
        for (int i = 0; i < 8; i += 2) {
            __half h0, l0, h1, l1;
            split_h(vals[i] * inv, h0, l0);
            split_h(vals[i + 1] * inv, h1, l1);
            *(__half2*)&g_ath[base + i] = __halves2half2(h0, h1);
            *(__half2*)&g_atl[base + i] = __halves2half2(l0, l1);
        }
    }
}

// ===========================================================================
// GEMM3 (fp16 3x split, NT): out = bias + attn[128,128] @ V^T[512,128]^T
// grid (4 h-blocks, 64 z), 256 threads, CTA 128x128, K = t = 128 (8 chunks).
// ===========================================================================
__global__ __launch_bounds__(256) void k_gemm3(const float* __restrict__ aspect,
                                               const float* __restrict__ polarity,
                                               float* __restrict__ out) {
    extern __shared__ __half sh[];
    const uint32_t sb = smem_to_u32(sh);
    const int tid = threadIdx.x;
    const int wid = tid >> 5, lane = tid & 31;
    const int g = lane >> 2, tig = lane & 3;
    const int sub = lane >> 3, r = lane & 7;
    const int wm = (wid & 3) * 32, wn = (wid >> 2) * 64;

    const int z = blockIdx.y;
    const int br = z >> 5, b = z & 31;
    const int h0 = blockIdx.x * 128;

    const int vsel = br ? 0 : 1;
    const __half* Ah = g_ath + (size_t)z * 16384;
    const __half* Al = g_atl + (size_t)z * 16384;
    const __half* Bh = g_vth + ((size_t)(vsel * 32 + b) * 512 + h0) * 128;
    const __half* Bl = g_vtl + ((size_t)(vsel * 32 + b) * 512 + h0) * 128;

    uint32_t offA[2];
#pragma unroll
    for (int fm = 0; fm < 2; fm++)
        offA[fm] = ((wm + fm * 16 + (sub & 1) * 8 + r) * ROWH + (sub >> 1) * 8) * 2;
    uint32_t offB[4];
#pragma unroll
    for (int p = 0; p < 4; p++)
        offB[p] = ((wn + p * 16 + (sub >> 1) * 8 + r) * ROWH + (sub & 1) * 8) * 2;

    const int lrow = tid >> 1, lh = (tid & 1) * 8;
    const uint32_t sdst = (uint32_t)(lrow * ROWH + lh) * 2;

    float acc[2][8][4] = {};

#define G3_LOAD(kc, buf)                                                    \
    {                                                                       \
        const uint32_t bb_ = sb + (buf) * BUFB;                             \
        const size_t so_ = (size_t)lrow * 128 + (kc) * 16 + lh;             \
        cp16(bb_ + 0 * MATB + sdst, Ah + so_);                              \
        cp16(bb_ + 1 * MATB + sdst, Al + so_);                              \
        cp16(bb_ + 2 * MATB + sdst, Bh + so_);                              \
        cp16(bb_ + 3 * MATB + sdst, Bl + so_);                              \
    }

    G3_LOAD(0, 0);
    cp_commit();
    G3_LOAD(1, 1);
    cp_commit();

#pragma unroll 1
    for (int c = 0; c < 8; c++) {
        cp_wait1();
        __syncthreads();
        const int buf = c % 3;
        if (c + 2 < 8) G3_LOAD(c + 2, (c + 2) % 3);
        cp_commit();
        const uint32_t mb = sb + buf * BUFB;

        uint32_t ah[2][4], al[2][4];
#pragma unroll
        for (int fm = 0; fm < 2; fm++) {
            ldsm4(ah[fm][0], ah[fm][1], ah[fm][2], ah[fm][3], mb + 0 * MATB + offA[fm]);
            ldsm4(al[fm][0], al[fm][1], al[fm][2], al[fm][3], mb + 1 * MATB + offA[fm]);
        }
        uint32_t bh[8][2], bl[8][2];
#pragma unroll
        for (int p = 0; p < 4; p++) {
            ldsm4(bh[2 * p][0], bh[2 * p][1], bh[2 * p + 1][0], bh[2 * p + 1][1],
                  mb + 2 * MATB + offB[p]);
            ldsm4(bl[2 * p][0], bl[2 * p][1], bl[2 * p + 1][0], bl[2 * p + 1][1],
                  mb + 3 * MATB + offB[p]);
        }
#pragma unroll
        for (int fm = 0; fm < 2; fm++)
#pragma unroll
            for (int fn = 0; fn < 8; fn++) {
                mma16816(acc[fm][fn], ah[fm], bh[fn]);
                mma16816(acc[fm][fn], ah[fm], bl[fn]);
                mma16816(acc[fm][fn], al[fm], bh[fn]);
            }
    }

    const float* bias = (br ? polarity : aspect) + (size_t)b * 128 * 512;
    float* C = out + (size_t)br * (32 * 128 * 512) + (size_t)b * 128 * 512;
#pragma unroll
    for (int fm = 0; fm < 2; fm++)
#pragma unroll
        for (int fn = 0; fn < 8; fn++) {
            const int row = wm + fm * 16 + g;
            const int col = h0 + wn + fn * 8 + tig * 2;
            size_t o = (size_t)row * 512 + col;
            float2 bv = *(const float2*)&bias[o];
            *(float2*)&C[o] =
                make_float2(bv.x + acc[fm][fn][0], bv.y + acc[fm][fn][1]);
            o += (size_t)8 * 512;
            bv = *(const float2*)&bias[o];
            *(float2*)&C[o] =
                make_float2(bv.x + acc[fm][fn][2], bv.y + acc[fm][fn][3]);
        }
}

// ---------------------------------------------------------------------------
extern "C" void kernel_launch(void* const* d_in, const int* in_sizes, int n_in,
                              void* d_out, int out_size) {
    const float* aspect = (const float*)d_in[0];
    const float* polarity = (const float*)d_in[1];
    const float* Gap = (const float*)d_in[2];
    const float* Gpa = (const float*)d_in[3];
    const float* va = (const float*)d_in[4];
    const float* vp = (const float*)d_in[5];
    float* out = (float*)d_out;

    cudaFuncSetAttribute(k_gemm1, cudaFuncAttributeMaxDynamicSharedMemorySize, GSMEM);
    cudaFuncSetAttribute(k_gemm2, cudaFuncAttributeMaxDynamicSharedMemorySize, GSMEM);
    cudaFuncSetAttribute(k_gemm3, cudaFuncAttributeMaxDynamicSharedMemorySize, GSMEM);

    k_prep_x<<<(2 * 32 * 128 * 512 / 4 + 255) / 256, 256>>>(aspect, polarity);
    k_prep_g<<<dim3(128, 16, 2), dim3(32, 8)>>>(Gap, Gpa);
    k_prep_v<<<dim3(16, 4, 64), dim3(32, 8)>>>(aspect, polarity);
    k_gemm1<<<dim3(32, 32, 2), 512, GSMEM>>>();
    k_gemm2<<<dim3(8, 64), 512, GSMEM>>>(va, vp);
    k_gemm3<<<dim3(4, 64), 256, GSMEM>>>(aspect, polarity, out);
}